// round 14
// baseline (speedup 1.0000x reference)
#include <cuda_runtime.h>
#include <cuda_bf16.h>
#include <cstdio>
#include <cstdint>

#define NND 20
#define CHN 512
#define HH  64
#define WW  64
#define HW  4096
#define CHW 2097152   // 512*64*64
#define NT2 256       // winograd F(4,3) tiles per plane (16x16)
#define NJ  36        // 6x6 transform coefficients

// Scratch planes: [V:1][Gr,Gu,Go:3][cs:1][-:3][h:20] = 28 planes
__device__ float g_buf[28ll * CHW];
__device__ float g_b[NND * CHN];            // per-node channel bias
__device__ float g_t[3 * NND * 9 * CHN];    // per-gate per-node per-tap const vectors
__device__ int   g_childcount[NND];
__device__ int   g_child[NND * NND];

// Winograd-transformed weights: [part(6)][split(2)][j(36)][o(512)][ci(512)] bf16
// parts: 0=reset_x 1=reset_h 2=update_x 3=update_h 4=output_x 5=output_h
__device__ __nv_bfloat16 g_uw[6ll * 2 * NJ * 512 * 512];
// Winograd-transformed inputs: 3 tensors, each [split(2)][j(36)][ci(512)][tile(256)]
__device__ __nv_bfloat16 g_wV[3ll * 2 * NJ * 512 * NT2];
#define VT_STRIDE (2ll * NJ * 512 * NT2)
// GEMM outputs: [conv(3)][j(36)][co(512)][tile(256)] fp32
__device__ float g_m[3ll * NJ * 512 * NT2];
#define M_STRIDE ((size_t)NJ * 512 * NT2)
// Per-node Winograd-domain R-conv results (kept until parent's gather)
__device__ float g_mr[(size_t)NND * NJ * 512 * NT2];
// mconv (1x1) bf16 split operands
__device__ __nv_bfloat16 g_vs[2ll * CHW];          // vis splits [split][ci][px]
__device__ __nv_bfloat16 g_mwsp[2ll * 512 * 512];  // mconv W splits [split][o][ci]

__device__ __forceinline__ float sigm(float v) { return 1.f / (1.f + expf(-v)); }

// ======================= low-level helpers (sm_100-safe) ====================
__device__ __forceinline__ uint32_t smem_u32(const void* p) {
    uint32_t a;
    asm("{ .reg .u64 t; cvta.to.shared.u64 t, %1; cvt.u32.u64 %0, t; }"
        : "=r"(a) : "l"(p));
    return a;
}
__device__ __forceinline__ void cp16(uint32_t dst, const void* src) {
    asm volatile("cp.async.cg.shared.global [%0], [%1], 16;"
        :: "r"(dst), "l"(src) : "memory");
}
__device__ __forceinline__ void ldm4(uint32_t* r, uint32_t addr) {
    asm volatile("ldmatrix.sync.aligned.m8n8.x4.shared.b16 {%0,%1,%2,%3}, [%4];"
        : "=r"(r[0]), "=r"(r[1]), "=r"(r[2]), "=r"(r[3]) : "r"(addr));
}
__device__ __forceinline__ void ldm4t(uint32_t* r, uint32_t addr) {
    asm volatile("ldmatrix.sync.aligned.m8n8.x4.trans.shared.b16 {%0,%1,%2,%3}, [%4];"
        : "=r"(r[0]), "=r"(r[1]), "=r"(r[2]), "=r"(r[3]) : "r"(addr));
}
__device__ __forceinline__ void mma_bf(float* c, const uint32_t* a,
                                       uint32_t b0, uint32_t b1) {
    asm volatile(
        "mma.sync.aligned.m16n8k16.row.col.f32.bf16.bf16.f32 "
        "{%0,%1,%2,%3}, {%4,%5,%6,%7}, {%8,%9}, {%0,%1,%2,%3};"
        : "+f"(c[0]), "+f"(c[1]), "+f"(c[2]), "+f"(c[3])
        : "r"(a[0]), "r"(a[1]), "r"(a[2]), "r"(a[3]), "r"(b0), "r"(b1));
}
#define SWZ(off) ((off) ^ (((off) >> 3) & 0x70))

// ---------------------------------------------------------------------------
// Tree prep
// ---------------------------------------------------------------------------
__global__ void prep_kernel(const int* __restrict__ adj) {
    int n = threadIdx.x;
    if (n < NND) {
        int cnt = 0;
        for (int k = 0; k < NND; k++)
            if (adj[n * NND + k] != 0) g_child[n * NND + cnt++] = k;
        g_childcount[n] = cnt;
    }
}

// ---------------------------------------------------------------------------
// b[n][o] = mconv_b[o] + sum_i mconv_w[o, 512+i] * lang[n, i]
// ---------------------------------------------------------------------------
__global__ void langbias_kernel(const float* __restrict__ lang,
                                const float* __restrict__ mw,
                                const float* __restrict__ mb) {
    int idx = blockIdx.x * 256 + threadIdx.x;
    if (idx >= NND * CHN) return;
    int n = idx / CHN, o = idx - n * CHN;
    const float* wp = mw + o * 812 + 512;
    const float* lp = lang + n * 300;
    float acc = mb[o];
    for (int i = 0; i < 300; i++) acc += wp[i] * lp[i];
    g_b[idx] = acc;
}

// ---------------------------------------------------------------------------
// t[g][n][tap][o] = sum_{i<512} Wg_x[o,i,tap] * b[n][i]
// ---------------------------------------------------------------------------
__global__ void tapconst_kernel(const float* __restrict__ rw,
                                const float* __restrict__ uw,
                                const float* __restrict__ ow) {
    __shared__ float bs[NND * CHN];  // 40KB
    int tid = threadIdx.x;
    for (int idx = tid; idx < NND * CHN; idx += 256) bs[idx] = g_b[idx];
    __syncthreads();
    int gidx = blockIdx.x * 256 + tid;
    int o   = gidx & (CHN - 1);
    int tap = (gidx >> 9) % 9;
    int g   = gidx / (CHN * 9);
    const float* w = (g == 0) ? rw : (g == 1) ? uw : ow;
    const float* wp = w + o * 9216 + tap;
    float acc[NND];
#pragma unroll
    for (int n = 0; n < NND; n++) acc[n] = 0.f;
    for (int i = 0; i < CHN; i++) {
        float wv = wp[i * 9];
#pragma unroll
        for (int n = 0; n < NND; n++) acc[n] += wv * bs[n * CHN + i];
    }
#pragma unroll
    for (int n = 0; n < NND; n++)
        g_t[((g * NND + n) * 9 + tap) * CHN + o] = acc[n];
}

// ---------------------------------------------------------------------------
// F(4,3) transform primitives
// ---------------------------------------------------------------------------
__device__ __forceinline__ void gtrans(float v0, float v1, float v2, float* u) {
    u[0] = 0.25f * v0;
    u[1] = -(v0 + v1 + v2) * (1.f / 6.f);
    u[2] = (-v0 + v1 - v2) * (1.f / 6.f);
    u[3] = (v0 + 2.f * v1 + 4.f * v2) * (1.f / 24.f);
    u[4] = (v0 - 2.f * v1 + 4.f * v2) * (1.f / 24.f);
    u[5] = v2;
}
__device__ __forceinline__ void bttrans(const float* v, float* w) {
    w[0] = 4.f * v[0] - 5.f * v[2] + v[4];
    w[1] = -4.f * v[1] - 4.f * v[2] + v[3] + v[4];
    w[2] = 4.f * v[1] - 4.f * v[2] - v[3] + v[4];
    w[3] = -2.f * v[1] - v[2] + 2.f * v[3] + v[4];
    w[4] = 2.f * v[1] - v[2] - 2.f * v[3] + v[4];
    w[5] = 4.f * v[1] - 5.f * v[3] + v[5];
}
__device__ __forceinline__ void attrans(const float* v, float* y) {
    y[0] = v[0] + v[1] + v[2] + v[3] + v[4];
    y[1] = v[1] - v[2] + 2.f * (v[3] - v[4]);
    y[2] = v[1] + v[2] + 4.f * (v[3] + v[4]);
    y[3] = v[1] - v[2] + 8.f * (v[3] - v[4]) + v[5];
}
__device__ __forceinline__ void fwd_write(const float (*psm)[67],
                                          __nv_bfloat16* __restrict__ V,
                                          int ci, int t) {
    int ty = t >> 4, tx = t & 15;
    float d[6][6], c[6][6];
#pragma unroll
    for (int i = 0; i < 6; i++)
#pragma unroll
        for (int j = 0; j < 6; j++)
            d[i][j] = psm[4 * ty + i][4 * tx + j];
#pragma unroll
    for (int j = 0; j < 6; j++) {
        float vin[6], vo[6];
#pragma unroll
        for (int i = 0; i < 6; i++) vin[i] = d[i][j];
        bttrans(vin, vo);
#pragma unroll
        for (int i = 0; i < 6; i++) c[i][j] = vo[i];
    }
#pragma unroll
    for (int i = 0; i < 6; i++) {
        float vo[6];
        bttrans(c[i], vo);
#pragma unroll
        for (int j = 0; j < 6; j++) {
            int j36 = i * 6 + j;
            size_t o = ((size_t)j36 * 512 + ci) * NT2 + t;
            __nv_bfloat16 h = __float2bfloat16(vo[j]);
            V[o] = h;
            V[o + (size_t)NJ * 512 * NT2] =
                __float2bfloat16(vo[j] - __bfloat162float(h));
        }
    }
}
__device__ __forceinline__ void inv_read(const float* __restrict__ M,
                                         int c, int t, float y16[4][4]) {
    float Z[6][6];
#pragma unroll
    for (int i = 0; i < 6; i++)
#pragma unroll
        for (int j = 0; j < 6; j++)
            Z[i][j] = M[((size_t)(i * 6 + j) * 512 + c) * NT2 + t];
    float cc[4][6];
#pragma unroll
    for (int j = 0; j < 6; j++) {
        float vin[6], vo[4];
#pragma unroll
        for (int i = 0; i < 6; i++) vin[i] = Z[i][j];
        attrans(vin, vo);
#pragma unroll
        for (int i = 0; i < 4; i++) cc[i][j] = vo[i];
    }
#pragma unroll
    for (int i = 0; i < 4; i++) attrans(cc[i], y16[i]);
}

// ---------------------------------------------------------------------------
// F(4,3) weight transform: U = G g G^T (6x6), split hi/lo bf16.
// ---------------------------------------------------------------------------
__global__ void wg_wprep_kernel(const float* __restrict__ rw,
                                const float* __restrict__ uw,
                                const float* __restrict__ ow) {
    int idx = blockIdx.x * 256 + threadIdx.x;
    if (idx >= 6 * 512 * 512) return;
    int ci = idx & 511;
    int o  = (idx >> 9) & 511;
    int part = idx >> 18;
    const float* w = (part < 2) ? rw : (part < 4) ? uw : ow;
    int coff = (part & 1) << 9;
    const float* gp = w + (size_t)o * 9216 + (size_t)(coff + ci) * 9;
    float g[9];
#pragma unroll
    for (int k = 0; k < 9; k++) g[k] = gp[k];
    float a[6][3];
#pragma unroll
    for (int j = 0; j < 3; j++) {
        float u[6];
        gtrans(g[j], g[3 + j], g[6 + j], u);
#pragma unroll
        for (int i = 0; i < 6; i++) a[i][j] = u[i];
    }
#pragma unroll
    for (int i = 0; i < 6; i++) {
        float U[6];
        gtrans(a[i][0], a[i][1], a[i][2], U);
#pragma unroll
        for (int j = 0; j < 6; j++) {
            int j36 = i * 6 + j;
            size_t base = ((((size_t)(part * 2) * NJ + j36) * 512 + o) << 9) + ci;
            __nv_bfloat16 h = __float2bfloat16(U[j]);
            g_uw[base] = h;
            g_uw[base + (size_t)NJ * 512 * 512] =
                __float2bfloat16(U[j] - __bfloat162float(h));
        }
    }
}

// ---------------------------------------------------------------------------
// mconv operand splits (vis + weights in one kernel)
// ---------------------------------------------------------------------------
__global__ void mc_split_kernel(const float* __restrict__ vis,
                                const float* __restrict__ mw) {
    int i = blockIdx.x * 256 + threadIdx.x;
    if (i < CHW) {
        float v = vis[i];
        __nv_bfloat16 h = __float2bfloat16(v);
        g_vs[i] = h;
        g_vs[(size_t)CHW + i] = __float2bfloat16(v - __bfloat162float(h));
    } else {
        int k = i - CHW;
        if (k < 512 * 512) {
            int o = k >> 9, ci = k & 511;
            float v = mw[o * 812 + ci];
            __nv_bfloat16 h = __float2bfloat16(v);
            g_mwsp[k] = h;
            g_mwsp[262144 + k] = __float2bfloat16(v - __bfloat162float(h));
        }
    }
}

// ---------------------------------------------------------------------------
// Plain input transform (for the initial V-plane): src[ci][64][64] -> V splits
// ---------------------------------------------------------------------------
__global__ void wg_itrans_kernel(const float* __restrict__ src,
                                 __nv_bfloat16* __restrict__ V) {
    __shared__ float psm[66][67];
    int ci = blockIdx.x, tid = threadIdx.x;
    const float* sp = src + (size_t)ci * HW;
    for (int i = tid; i < 66 * 67; i += 256) (&psm[0][0])[i] = 0.f;
    __syncthreads();
    for (int i = tid; i < 4096; i += 256)
        psm[(i >> 6) + 1][(i & 63) + 1] = sp[i];
    __syncthreads();
    fwd_write(psm, V, ci, tid);
}

// ---------------------------------------------------------------------------
// FUSED gather (with on-the-fly R inverse transform) + dual forward transform.
// Per-ci block, internal nodes only. Writes cs plane + V0 (cs) + V1 (rh).
// ---------------------------------------------------------------------------
__global__ void gather_itrans_kernel(int n, const float* __restrict__ rb,
                                     __nv_bfloat16* __restrict__ V0,
                                     __nv_bfloat16* __restrict__ V1) {
    int cnt = g_childcount[n];
    if (cnt == 0) return;
    __shared__ float csm[66][67];
    __shared__ float rsm[66][67];
    int ci = blockIdx.x, tid = threadIdx.x;
    for (int i = tid; i < 66 * 67; i += 256) {
        (&csm[0][0])[i] = 0.f;
        (&rsm[0][0])[i] = 0.f;
    }
    __syncthreads();
    float tv[9];
#pragma unroll
    for (int k = 0; k < 9; k++)
        tv[k] = g_t[((0 * NND + n) * 9 + k) * CHN + ci];
    float rbc = rb[ci];
    int ty = tid >> 4, tx = tid & 15;
    const float* Gr = g_buf + 1 * CHW + (size_t)ci * HW;
    float base16[4][4];
#pragma unroll
    for (int i = 0; i < 4; i++)
#pragma unroll
        for (int j = 0; j < 4; j++) {
            int y = 4 * ty + i, x = 4 * tx + j;
            int ky0 = (y == 0), ky1 = 2 - (y == HH - 1);
            int kx0 = (x == 0), kx1 = 2 - (x == WW - 1);
            float cr = 0.f;
            for (int ky = ky0; ky <= ky1; ky++)
                for (int kx = kx0; kx <= kx1; kx++)
                    cr += tv[ky * 3 + kx];
            base16[i][j] = Gr[y * WW + x] + rbc + cr;
        }
    float cs16[4][4], rh16[4][4];
#pragma unroll
    for (int i = 0; i < 4; i++)
#pragma unroll
        for (int j = 0; j < 4; j++) { cs16[i][j] = 0.f; rh16[i][j] = 0.f; }
    for (int c0 = 0; c0 < cnt; c0++) {
        int k = g_child[n * NND + c0];
        float r16[4][4];
        inv_read(g_mr + (size_t)k * M_STRIDE, ci, tid, r16);
        const float* hp = g_buf + (size_t)(8 + k) * CHW + (size_t)ci * HW;
#pragma unroll
        for (int i = 0; i < 4; i++) {
            float4 hv4 = *reinterpret_cast<const float4*>(
                hp + (4 * ty + i) * WW + 4 * tx);
            float hv[4] = {hv4.x, hv4.y, hv4.z, hv4.w};
#pragma unroll
            for (int j = 0; j < 4; j++) {
                float rr = sigm(base16[i][j] + r16[i][j]);
                cs16[i][j] += hv[j];
                rh16[i][j] += rr * hv[j];
            }
        }
    }
    float* csout = g_buf + 4 * CHW + (size_t)ci * HW;
#pragma unroll
    for (int i = 0; i < 4; i++) {
        int y = 4 * ty + i;
        *reinterpret_cast<float4*>(csout + y * WW + 4 * tx) =
            make_float4(cs16[i][0], cs16[i][1], cs16[i][2], cs16[i][3]);
#pragma unroll
        for (int j = 0; j < 4; j++) {
            csm[y + 1][4 * tx + j + 1] = cs16[i][j];
            rsm[y + 1][4 * tx + j + 1] = rh16[i][j];
        }
    }
    __syncthreads();
    fwd_write(csm, V0, ci, tid);
    fwd_write(rsm, V1, ci, tid);
}

// ---------------------------------------------------------------------------
// FUSED inverse(U,O) + combine + forward transform of h (all nodes).
// Per-channel block. Root (n==0): writes out, no transform.
// ---------------------------------------------------------------------------
__global__ void inv_combine_kernel(int n, const float* __restrict__ ub,
                                   const float* __restrict__ ob,
                                   float* __restrict__ outroot,
                                   __nv_bfloat16* __restrict__ V2) {
    __shared__ float hsm[66][67];
    int c = blockIdx.x, tid = threadIdx.x;
    bool haskids = g_childcount[n] > 0;
    for (int i = tid; i < 66 * 67; i += 256) (&hsm[0][0])[i] = 0.f;
    __syncthreads();
    int t = tid, ty = t >> 4, tx = t & 15;
    float u16[4][4], o16[4][4];
    if (haskids) {
        inv_read(g_m, c, t, u16);
        inv_read(g_m + M_STRIDE, c, t, o16);
    }
    float tu9[9], to9[9];
#pragma unroll
    for (int k = 0; k < 9; k++) {
        tu9[k] = g_t[((1 * NND + n) * 9 + k) * CHN + c];
        to9[k] = g_t[((2 * NND + n) * 9 + k) * CHN + c];
    }
    float ubc = ub[c], obc = ob[c];
    const float* Gu = g_buf + 2 * CHW + (size_t)c * HW;
    const float* Go = g_buf + 3 * CHW + (size_t)c * HW;
    const float* CS = g_buf + 4 * CHW + (size_t)c * HW;
    float* hpl = (n == 0) ? (outroot + (size_t)c * HW)
                          : (g_buf + (size_t)(8 + n) * CHW + (size_t)c * HW);
#pragma unroll
    for (int i = 0; i < 4; i++) {
#pragma unroll
        for (int j = 0; j < 4; j++) {
            int y = 4 * ty + i, x = 4 * tx + j;
            int p = y * WW + x;
            int ky0 = (y == 0), ky1 = 2 - (y == HH - 1);
            int kx0 = (x == 0), kx1 = 2 - (x == WW - 1);
            float cu = 0.f, co = 0.f;
            for (int ky = ky0; ky <= ky1; ky++)
                for (int kx = kx0; kx <= kx1; kx++) {
                    cu += tu9[ky * 3 + kx];
                    co += to9[ky * 3 + kx];
                }
            float uacc = haskids ? u16[i][j] : 0.f;
            float oacc = haskids ? o16[i][j] : 0.f;
            float cs   = haskids ? CS[p] : 0.f;
            float z  = sigm(Gu[p] + ubc + cu + uacc);
            float ri = tanhf(Go[p] + obc + co + oacc);
            float h = (1.f - z) * ri + z * cs;
            hpl[p] = h;
            hsm[y + 1][x + 1] = h;
        }
    }
    if (n > 0) {
        __syncthreads();
        fwd_write(hsm, V2, c, t);
    }
}

// ---------------------------------------------------------------------------
// Winograd GEMM: per j, M_j[co][tile] = U_j[co][ci] * V_j[ci][tile]
// bf16 3-split, fp32 accum. K=512 -> 24 stages of 64.
// CTA 128co x 128tile, 4 warps (2m x 2n). grid (2, 4, 36*nconv).
// ONE __syncthreads per stage (3-slot pipeline makes the trailing one redundant).
// ---------------------------------------------------------------------------
#define WG_SMEM 98304   // 3 x (A 16KB + B 16KB)

__device__ __forceinline__ void wg_issue_stage(
    int s, uint32_t sA, int tid, int tileB, int coB, int part, int j,
    const __nv_bfloat16* V) {
    int s3 = s >> 3;
    int cb = (s & 7) << 6;
    int wsplit = (s3 == 1) ? 1 : 0;
    int xsplit = (s3 == 2) ? 1 : 0;
    const __nv_bfloat16* Abase =
        g_uw + ((((size_t)(part * 2 + wsplit) * NJ + j) * 512 + coB) << 9) + cb;
    const __nv_bfloat16* Bbase =
        V + (((size_t)(xsplit * NJ + j) * 512 + cb) * NT2) + tileB;
    uint32_t slot = sA + (s % 3) * 32768;
#pragma unroll
    for (int it = 0; it < 8; it++) {
        int i = tid + it * 128;
        int o = i >> 3, q = i & 7;
        cp16(slot + SWZ(o * 128 + q * 16), Abase + ((size_t)o << 9) + q * 8);
    }
#pragma unroll
    for (int it = 0; it < 8; it++) {
        int i = tid + it * 128;
        int k = i >> 4, cc = i & 15;
        cp16(slot + 16384 + k * 256 + ((cc ^ (k & 7)) << 4),
             Bbase + (size_t)k * NT2 + cc * 8);
    }
    asm volatile("cp.async.commit_group;" ::: "memory");
}

__global__ __launch_bounds__(128)
void wg_gemm_kernel(const __nv_bfloat16* __restrict__ V0, int p0,
                    const __nv_bfloat16* __restrict__ V1, int p1,
                    const __nv_bfloat16* __restrict__ V2, int p2,
                    float* __restrict__ M0, float* __restrict__ M1,
                    float* __restrict__ M2, int flag_n) {
    if (flag_n >= 0 && g_childcount[flag_n] == 0) return;
    extern __shared__ char smem[];
    uint32_t sA = smem_u32(smem);
    int which = blockIdx.z / NJ;
    int j = blockIdx.z - which * NJ;
    const __nv_bfloat16* V = (which == 0) ? V0 : (which == 1) ? V1 : V2;
    int part = (which == 0) ? p0 : (which == 1) ? p1 : p2;
    float* M = (which == 0) ? M0 : (which == 1) ? M1 : M2;

    int tid = threadIdx.x;
    int wid = tid >> 5, lane = tid & 31;
    int tileB = blockIdx.x * 128;
    int coB   = blockIdx.y * 128;
    int wm = wid >> 1;
    int wn = wid & 1;

    float acc[4][8][4];
#pragma unroll
    for (int a = 0; a < 4; a++)
#pragma unroll
        for (int b = 0; b < 8; b++)
#pragma unroll
            for (int c = 0; c < 4; c++) acc[a][b][c] = 0.f;

    wg_issue_stage(0, sA, tid, tileB, coB, part, j, V);
    wg_issue_stage(1, sA, tid, tileB, coB, part, j, V);

    for (int s = 0; s < 24; s++) {
        asm volatile("cp.async.wait_group 1;" ::: "memory");
        __syncthreads();
        if (s + 2 < 24)
            wg_issue_stage(s + 2, sA, tid, tileB, coB, part, j, V);
        uint32_t Ab = sA + (s % 3) * 32768;
        uint32_t Bb = Ab + 16384;
#pragma unroll
        for (int ks = 0; ks < 4; ks++) {
            uint32_t afr[4][4];
#pragma unroll
            for (int mi = 0; mi < 4; mi++) {
                int row = wm * 64 + mi * 16 + (lane & 15);
                int k16 = ks * 2 + (lane >> 4);
                ldm4(afr[mi], Ab + SWZ(row * 128 + k16 * 16));
            }
            uint32_t bfr[4][4];
#pragma unroll
            for (int ng = 0; ng < 4; ng++) {
                int krow = ks * 16 + (lane & 7) + (((lane >> 3) & 1) << 3);
                int cc   = ((wn * 64 + ng * 16) >> 3) + (lane >> 4);
                ldm4t(bfr[ng], Bb + krow * 256 + ((cc ^ (krow & 7)) << 4));
            }
#pragma unroll
            for (int mi = 0; mi < 4; mi++)
#pragma unroll
                for (int ng = 0; ng < 4; ng++) {
                    mma_bf(acc[mi][ng * 2 + 0], afr[mi], bfr[ng][0], bfr[ng][1]);
                    mma_bf(acc[mi][ng * 2 + 1], afr[mi], bfr[ng][2], bfr[ng][3]);
                }
        }
    }

#pragma unroll
    for (int mi = 0; mi < 4; mi++) {
        int row0 = coB + wm * 64 + mi * 16 + (lane >> 2);
        float* mp0 = M + ((size_t)j * 512 + row0) * NT2 + tileB;
#pragma unroll
        for (int nj = 0; nj < 8; nj++) {
            int col = wn * 64 + nj * 8 + (lane & 3) * 2;
            *reinterpret_cast<float2*>(mp0 + col) =
                make_float2(acc[mi][nj][0], acc[mi][nj][1]);
            *reinterpret_cast<float2*>(mp0 + 8 * NT2 + col) =
                make_float2(acc[mi][nj][2], acc[mi][nj][3]);
        }
    }
}

// ---------------------------------------------------------------------------
// mconv 1x1 GEMM via bf16 3-split mma: out[co][px] = mw[:, :512] @ vis
// ---------------------------------------------------------------------------
__device__ __forceinline__ void mc_issue_stage(int s, uint32_t sA, int tid,
                                               int pxB, int coB) {
    int s3 = s >> 3;
    int cb = (s & 7) << 6;
    int wsplit = (s3 == 1) ? 1 : 0;
    int xsplit = (s3 == 2) ? 1 : 0;
    const __nv_bfloat16* Abase = g_mwsp + (size_t)wsplit * 262144 + (coB << 9) + cb;
    const __nv_bfloat16* Bbase = g_vs + (size_t)xsplit * CHW + (size_t)cb * HW + pxB;
    uint32_t slot = sA + (s % 3) * 32768;
#pragma unroll
    for (int it = 0; it < 8; it++) {
        int i = tid + it * 128;
        int o = i >> 3, q = i & 7;
        cp16(slot + SWZ(o * 128 + q * 16), Abase + ((size_t)o << 9) + q * 8);
    }
#pragma unroll
    for (int it = 0; it < 8; it++) {
        int i = tid + it * 128;
        int k = i >> 4, cc = i & 15;
        cp16(slot + 16384 + k * 256 + ((cc ^ (k & 7)) << 4),
             Bbase + (size_t)k * HW + cc * 8);
    }
    asm volatile("cp.async.commit_group;" ::: "memory");
}

__global__ __launch_bounds__(128)
void mc_gemm_kernel(float* __restrict__ out) {
    extern __shared__ char smem[];
    uint32_t sA = smem_u32(smem);
    int tid = threadIdx.x;
    int wid = tid >> 5, lane = tid & 31;
    int pxB = blockIdx.x * 128;
    int coB = blockIdx.y * 128;
    int wm = wid >> 1;
    int wn = wid & 1;

    float acc[4][8][4];
#pragma unroll
    for (int a = 0; a < 4; a++)
#pragma unroll
        for (int b = 0; b < 8; b++)
#pragma unroll
            for (int c = 0; c < 4; c++) acc[a][b][c] = 0.f;

    mc_issue_stage(0, sA, tid, pxB, coB);
    mc_issue_stage(1, sA, tid, pxB, coB);

    for (int s = 0; s < 24; s++) {
        asm volatile("cp.async.wait_group 1;" ::: "memory");
        __syncthreads();
        if (s + 2 < 24)
            mc_issue_stage(s + 2, sA, tid, pxB, coB);
        uint32_t Ab = sA + (s % 3) * 32768;
        uint32_t Bb = Ab + 16384;
#pragma unroll
        for (int ks = 0; ks < 4; ks++) {
            uint32_t afr[4][4];
#pragma unroll
            for (int mi = 0; mi < 4; mi++) {
                int row = wm * 64 + mi * 16 + (lane & 15);
                int k16 = ks * 2 + (lane >> 4);
                ldm4(afr[mi], Ab + SWZ(row * 128 + k16 * 16));
            }
            uint32_t bfr[4][4];
#pragma unroll
            for (int ng = 0; ng < 4; ng++) {
                int krow = ks * 16 + (lane & 7) + (((lane >> 3) & 1) << 3);
                int cc   = ((wn * 64 + ng * 16) >> 3) + (lane >> 4);
                ldm4t(bfr[ng], Bb + krow * 256 + ((cc ^ (krow & 7)) << 4));
            }
#pragma unroll
            for (int mi = 0; mi < 4; mi++)
#pragma unroll
                for (int ng = 0; ng < 4; ng++) {
                    mma_bf(acc[mi][ng * 2 + 0], afr[mi], bfr[ng][0], bfr[ng][1]);
                    mma_bf(acc[mi][ng * 2 + 1], afr[mi], bfr[ng][2], bfr[ng][3]);
                }
        }
    }

#pragma unroll
    for (int mi = 0; mi < 4; mi++) {
        int row0 = coB + wm * 64 + mi * 16 + (lane >> 2);
        float* op = out + (size_t)row0 * HW + pxB;
#pragma unroll
        for (int nj = 0; nj < 8; nj++) {
            int col = wn * 64 + nj * 8 + (lane & 3) * 2;
            *reinterpret_cast<float2*>(op + col) =
                make_float2(acc[mi][nj][0], acc[mi][nj][1]);
            *reinterpret_cast<float2*>(op + 8 * HW + col) =
                make_float2(acc[mi][nj][2], acc[mi][nj][3]);
        }
    }
}

// ---------------------------------------------------------------------------
// Plain inverse transform (initial Gr/Gu/Go convs)
// ---------------------------------------------------------------------------
__global__ void wg_inv_kernel(float* __restrict__ D0, float* __restrict__ D1,
                              float* __restrict__ D2) {
    int conv = blockIdx.y;
    const float* M = g_m + (size_t)conv * M_STRIDE;
    float* D = (conv == 0) ? D0 : (conv == 1) ? D1 : D2;
    int e = blockIdx.x * 256 + threadIdx.x;
    int co = e >> 8, t = e & (NT2 - 1);
    float y16[4][4];
    inv_read(M, co, t, y16);
    int ty = t >> 4, tx = t & 15;
    float* op = D + (size_t)co * HW + (4 * ty) * WW + 4 * tx;
#pragma unroll
    for (int i = 0; i < 4; i++)
        *reinterpret_cast<float4*>(op + i * WW) =
            make_float4(y16[i][0], y16[i][1], y16[i][2], y16[i][3]);
}

// ---------------------------------------------------------------------------
extern "C" void kernel_launch(void* const* d_in, const int* in_sizes, int n_in,
                              void* d_out, int out_size) {
    const float* vis  = (const float*)d_in[0];
    const float* lang = (const float*)d_in[1];
    const int*   adj  = (const int*)d_in[2];
    const float* mw   = (const float*)d_in[3];
    const float* mb   = (const float*)d_in[4];
    const float* rw   = (const float*)d_in[5];
    const float* rb   = (const float*)d_in[6];
    const float* uw   = (const float*)d_in[7];
    const float* ub   = (const float*)d_in[8];
    const float* ow   = (const float*)d_in[9];
    const float* ob   = (const float*)d_in[10];
    float* out = (float*)d_out;

    float* buf = nullptr;
    cudaGetSymbolAddress((void**)&buf, g_buf);
    __nv_bfloat16* wv = nullptr;
    cudaGetSymbolAddress((void**)&wv, g_wV);
    float* m = nullptr;
    cudaGetSymbolAddress((void**)&m, g_m);
    float* mr = nullptr;
    cudaGetSymbolAddress((void**)&mr, g_mr);
    __nv_bfloat16* V0 = wv;
    __nv_bfloat16* V1 = wv + VT_STRIDE;
    __nv_bfloat16* V2 = wv + 2 * VT_STRIDE;

    static bool init_done = false;
    static cudaStream_t s1 = nullptr;
    static cudaEvent_t evF = nullptr, evJ = nullptr;
    if (!init_done) {
        cudaFuncSetAttribute(wg_gemm_kernel,
                             cudaFuncAttributeMaxDynamicSharedMemorySize, WG_SMEM);
        cudaFuncSetAttribute(mc_gemm_kernel,
                             cudaFuncAttributeMaxDynamicSharedMemorySize, WG_SMEM);
        cudaStreamCreateWithFlags(&s1, cudaStreamNonBlocking);
        cudaEventCreateWithFlags(&evF, cudaEventDisableTiming);
        cudaEventCreateWithFlags(&evJ, cudaEventDisableTiming);
        init_done = true;
    }

    dim3 wgrid1(2, 4, NJ);               // winograd gemm, 1 conv
    dim3 wgrid2(2, 4, 2 * NJ);           // 2 convs
    dim3 wgrid3(2, 4, 3 * NJ);           // 3 convs
    dim3 mcg(32, 4);                     // mconv gemm
    dim3 inv3(512, 3);

    // ---- fork: weight-prep path on s1, data path on default stream ----
    cudaEventRecord(evF, 0);
    cudaStreamWaitEvent(s1, evF, 0);

    prep_kernel<<<1, 32, 0, s1>>>(adj);
    langbias_kernel<<<40, 256, 0, s1>>>(lang, mw, mb);
    tapconst_kernel<<<54, 256, 0, s1>>>(rw, uw, ow);
    wg_wprep_kernel<<<6144, 256, 0, s1>>>(rw, uw, ow);
    cudaEventRecord(evJ, s1);

    mc_split_kernel<<<9216, 256>>>(vis, mw);
    mc_gemm_kernel<<<mcg, 128, WG_SMEM>>>(buf);       // V-plane (vis part of mconv)
    wg_itrans_kernel<<<512, 256>>>(buf, V0);

    cudaStreamWaitEvent(0, evJ, 0);                   // join before weights used
    // -------------------------------------------------------------------

    // shared convs of V (x-part weights of the 3 gates): Gr, Gu, Go
    wg_gemm_kernel<<<wgrid3, 128, WG_SMEM>>>(V0, 0, V0, 2, V0, 4,
                                             m, m + M_STRIDE, m + 2 * M_STRIDE, -1);
    wg_inv_kernel<<<inv3, 256>>>(buf + 1 * CHW, buf + 2 * CHW, buf + 3 * CHW);

    // nodes in decreasing index = valid topological order (parent(i) < i)
    for (int n = NND - 1; n >= 0; n--) {
        // fused gather (+R inverse) + forward transforms of cs, rh (skips on leaf)
        gather_itrans_kernel<<<512, 256>>>(n, rb, V0, V1);
        // U = conv(cs, Wu_h), O = conv(rh, Wo_h) (skips on leaf)
        wg_gemm_kernel<<<wgrid2, 128, WG_SMEM>>>(V0, 3, V1, 5, V1, 5,
                                                 m, m + M_STRIDE, m + 2 * M_STRIDE, n);
        // fused inverse(U,O) + combine (+ forward transform of h when n>0)
        inv_combine_kernel<<<512, 256>>>(n, ub, ob, out, V2);
        if (n > 0)  // R[n] (Winograd domain, inverse deferred to parent's gather)
            wg_gemm_kernel<<<wgrid1, 128, WG_SMEM>>>(
                V2, 1, V2, 1, V2, 1,
                mr + (size_t)n * M_STRIDE, nullptr, nullptr, -1);
    }
}

// round 15
// speedup vs baseline: 1.0213x; 1.0213x over previous
#include <cuda_runtime.h>
#include <cuda_bf16.h>
#include <cstdio>
#include <cstdint>

#define NND 20
#define CHN 512
#define HH  64
#define WW  64
#define HW  4096
#define CHW 2097152   // 512*64*64
#define NT2 256       // winograd F(4,3) tiles per plane (16x16)
#define NJ  36        // 6x6 transform coefficients

// Scratch planes: [V:1][Gr,Gu,Go:3][cs:1][-:3][h:20] = 28 planes
__device__ float g_buf[28ll * CHW];
__device__ float g_b[NND * CHN];            // per-node channel bias
__device__ float g_t[3 * NND * 9 * CHN];    // per-gate per-node per-tap const vectors
__device__ int   g_childcount[NND];
__device__ int   g_child[NND * NND];

// Winograd-transformed weights: [part(6)][split(2)][j(36)][o(512)][ci(512)] bf16
// parts: 0=reset_x 1=reset_h 2=update_x 3=update_h 4=output_x 5=output_h
__device__ __nv_bfloat16 g_uw[6ll * 2 * NJ * 512 * 512];
// Winograd-transformed inputs: 3 tensors, each [split(2)][j(36)][ci(512)][tile(256)]
__device__ __nv_bfloat16 g_wV[3ll * 2 * NJ * 512 * NT2];
#define VT_STRIDE (2ll * NJ * 512 * NT2)
// GEMM outputs: [conv(3)][j(36)][co(512)][tile(256)] fp32
__device__ float g_m[3ll * NJ * 512 * NT2];
#define M_STRIDE ((size_t)NJ * 512 * NT2)
// Per-node Winograd-domain R-conv results (kept until parent's gather)
__device__ float g_mr[(size_t)NND * NJ * 512 * NT2];
// mconv (1x1) bf16 split operands
__device__ __nv_bfloat16 g_vs[2ll * CHW];          // vis splits [split][ci][px]
__device__ __nv_bfloat16 g_mwsp[2ll * 512 * 512];  // mconv W splits [split][o][ci]

__device__ __forceinline__ float sigm(float v) { return 1.f / (1.f + expf(-v)); }

// ======================= low-level helpers (sm_100-safe) ====================
__device__ __forceinline__ uint32_t smem_u32(const void* p) {
    uint32_t a;
    asm("{ .reg .u64 t; cvta.to.shared.u64 t, %1; cvt.u32.u64 %0, t; }"
        : "=r"(a) : "l"(p));
    return a;
}
__device__ __forceinline__ void cp16(uint32_t dst, const void* src) {
    asm volatile("cp.async.cg.shared.global [%0], [%1], 16;"
        :: "r"(dst), "l"(src) : "memory");
}
__device__ __forceinline__ void ldm4(uint32_t* r, uint32_t addr) {
    asm volatile("ldmatrix.sync.aligned.m8n8.x4.shared.b16 {%0,%1,%2,%3}, [%4];"
        : "=r"(r[0]), "=r"(r[1]), "=r"(r[2]), "=r"(r[3]) : "r"(addr));
}
__device__ __forceinline__ void ldm4t(uint32_t* r, uint32_t addr) {
    asm volatile("ldmatrix.sync.aligned.m8n8.x4.trans.shared.b16 {%0,%1,%2,%3}, [%4];"
        : "=r"(r[0]), "=r"(r[1]), "=r"(r[2]), "=r"(r[3]) : "r"(addr));
}
__device__ __forceinline__ void mma_bf(float* c, const uint32_t* a,
                                       uint32_t b0, uint32_t b1) {
    asm volatile(
        "mma.sync.aligned.m16n8k16.row.col.f32.bf16.bf16.f32 "
        "{%0,%1,%2,%3}, {%4,%5,%6,%7}, {%8,%9}, {%0,%1,%2,%3};"
        : "+f"(c[0]), "+f"(c[1]), "+f"(c[2]), "+f"(c[3])
        : "r"(a[0]), "r"(a[1]), "r"(a[2]), "r"(a[3]), "r"(b0), "r"(b1));
}
#define SWZ(off) ((off) ^ (((off) >> 3) & 0x70))

// ---------------------------------------------------------------------------
// Tree prep
// ---------------------------------------------------------------------------
__global__ void prep_kernel(const int* __restrict__ adj) {
    int n = threadIdx.x;
    if (n < NND) {
        int cnt = 0;
        for (int k = 0; k < NND; k++)
            if (adj[n * NND + k] != 0) g_child[n * NND + cnt++] = k;
        g_childcount[n] = cnt;
    }
}

// ---------------------------------------------------------------------------
// b[n][o] = mconv_b[o] + sum_i mconv_w[o, 512+i] * lang[n, i]
// ---------------------------------------------------------------------------
__global__ void langbias_kernel(const float* __restrict__ lang,
                                const float* __restrict__ mw,
                                const float* __restrict__ mb) {
    int idx = blockIdx.x * 256 + threadIdx.x;
    if (idx >= NND * CHN) return;
    int n = idx / CHN, o = idx - n * CHN;
    const float* wp = mw + o * 812 + 512;
    const float* lp = lang + n * 300;
    float acc = mb[o];
    for (int i = 0; i < 300; i++) acc += wp[i] * lp[i];
    g_b[idx] = acc;
}

// ---------------------------------------------------------------------------
// t[g][n][tap][o] = sum_{i<512} Wg_x[o,i,tap] * b[n][i]
// ---------------------------------------------------------------------------
__global__ void tapconst_kernel(const float* __restrict__ rw,
                                const float* __restrict__ uw,
                                const float* __restrict__ ow) {
    __shared__ float bs[NND * CHN];  // 40KB
    int tid = threadIdx.x;
    for (int idx = tid; idx < NND * CHN; idx += 256) bs[idx] = g_b[idx];
    __syncthreads();
    int gidx = blockIdx.x * 256 + tid;
    int o   = gidx & (CHN - 1);
    int tap = (gidx >> 9) % 9;
    int g   = gidx / (CHN * 9);
    const float* w = (g == 0) ? rw : (g == 1) ? uw : ow;
    const float* wp = w + o * 9216 + tap;
    float acc[NND];
#pragma unroll
    for (int n = 0; n < NND; n++) acc[n] = 0.f;
    for (int i = 0; i < CHN; i++) {
        float wv = wp[i * 9];
#pragma unroll
        for (int n = 0; n < NND; n++) acc[n] += wv * bs[n * CHN + i];
    }
#pragma unroll
    for (int n = 0; n < NND; n++)
        g_t[((g * NND + n) * 9 + tap) * CHN + o] = acc[n];
}

// ---------------------------------------------------------------------------
// F(4,3) transform primitives
// ---------------------------------------------------------------------------
__device__ __forceinline__ void gtrans(float v0, float v1, float v2, float* u) {
    u[0] = 0.25f * v0;
    u[1] = -(v0 + v1 + v2) * (1.f / 6.f);
    u[2] = (-v0 + v1 - v2) * (1.f / 6.f);
    u[3] = (v0 + 2.f * v1 + 4.f * v2) * (1.f / 24.f);
    u[4] = (v0 - 2.f * v1 + 4.f * v2) * (1.f / 24.f);
    u[5] = v2;
}
__device__ __forceinline__ void bttrans(const float* v, float* w) {
    w[0] = 4.f * v[0] - 5.f * v[2] + v[4];
    w[1] = -4.f * v[1] - 4.f * v[2] + v[3] + v[4];
    w[2] = 4.f * v[1] - 4.f * v[2] - v[3] + v[4];
    w[3] = -2.f * v[1] - v[2] + 2.f * v[3] + v[4];
    w[4] = 2.f * v[1] - v[2] - 2.f * v[3] + v[4];
    w[5] = 4.f * v[1] - 5.f * v[3] + v[5];
}
__device__ __forceinline__ void attrans(const float* v, float* y) {
    y[0] = v[0] + v[1] + v[2] + v[3] + v[4];
    y[1] = v[1] - v[2] + 2.f * (v[3] - v[4]);
    y[2] = v[1] + v[2] + 4.f * (v[3] + v[4]);
    y[3] = v[1] - v[2] + 8.f * (v[3] - v[4]) + v[5];
}
__device__ __forceinline__ void fwd_write(const float (*psm)[67],
                                          __nv_bfloat16* __restrict__ V,
                                          int ci, int t) {
    int ty = t >> 4, tx = t & 15;
    float d[6][6], c[6][6];
#pragma unroll
    for (int i = 0; i < 6; i++)
#pragma unroll
        for (int j = 0; j < 6; j++)
            d[i][j] = psm[4 * ty + i][4 * tx + j];
#pragma unroll
    for (int j = 0; j < 6; j++) {
        float vin[6], vo[6];
#pragma unroll
        for (int i = 0; i < 6; i++) vin[i] = d[i][j];
        bttrans(vin, vo);
#pragma unroll
        for (int i = 0; i < 6; i++) c[i][j] = vo[i];
    }
#pragma unroll
    for (int i = 0; i < 6; i++) {
        float vo[6];
        bttrans(c[i], vo);
#pragma unroll
        for (int j = 0; j < 6; j++) {
            int j36 = i * 6 + j;
            size_t o = ((size_t)j36 * 512 + ci) * NT2 + t;
            __nv_bfloat16 h = __float2bfloat16(vo[j]);
            V[o] = h;
            V[o + (size_t)NJ * 512 * NT2] =
                __float2bfloat16(vo[j] - __bfloat162float(h));
        }
    }
}
__device__ __forceinline__ void inv_read(const float* __restrict__ M,
                                         int c, int t, float y16[4][4]) {
    float Z[6][6];
#pragma unroll
    for (int i = 0; i < 6; i++)
#pragma unroll
        for (int j = 0; j < 6; j++)
            Z[i][j] = M[((size_t)(i * 6 + j) * 512 + c) * NT2 + t];
    float cc[4][6];
#pragma unroll
    for (int j = 0; j < 6; j++) {
        float vin[6], vo[4];
#pragma unroll
        for (int i = 0; i < 6; i++) vin[i] = Z[i][j];
        attrans(vin, vo);
#pragma unroll
        for (int i = 0; i < 4; i++) cc[i][j] = vo[i];
    }
#pragma unroll
    for (int i = 0; i < 4; i++) attrans(cc[i], y16[i]);
}

// ---------------------------------------------------------------------------
// F(4,3) weight transform: U = G g G^T (6x6), split hi/lo bf16.
// ---------------------------------------------------------------------------
__global__ void wg_wprep_kernel(const float* __restrict__ rw,
                                const float* __restrict__ uw,
                                const float* __restrict__ ow) {
    int idx = blockIdx.x * 256 + threadIdx.x;
    if (idx >= 6 * 512 * 512) return;
    int ci = idx & 511;
    int o  = (idx >> 9) & 511;
    int part = idx >> 18;
    const float* w = (part < 2) ? rw : (part < 4) ? uw : ow;
    int coff = (part & 1) << 9;
    const float* gp = w + (size_t)o * 9216 + (size_t)(coff + ci) * 9;
    float g[9];
#pragma unroll
    for (int k = 0; k < 9; k++) g[k] = gp[k];
    float a[6][3];
#pragma unroll
    for (int j = 0; j < 3; j++) {
        float u[6];
        gtrans(g[j], g[3 + j], g[6 + j], u);
#pragma unroll
        for (int i = 0; i < 6; i++) a[i][j] = u[i];
    }
#pragma unroll
    for (int i = 0; i < 6; i++) {
        float U[6];
        gtrans(a[i][0], a[i][1], a[i][2], U);
#pragma unroll
        for (int j = 0; j < 6; j++) {
            int j36 = i * 6 + j;
            size_t base = ((((size_t)(part * 2) * NJ + j36) * 512 + o) << 9) + ci;
            __nv_bfloat16 h = __float2bfloat16(U[j]);
            g_uw[base] = h;
            g_uw[base + (size_t)NJ * 512 * 512] =
                __float2bfloat16(U[j] - __bfloat162float(h));
        }
    }
}

// ---------------------------------------------------------------------------
// mconv operand splits (vis + weights in one kernel)
// ---------------------------------------------------------------------------
__global__ void mc_split_kernel(const float* __restrict__ vis,
                                const float* __restrict__ mw) {
    int i = blockIdx.x * 256 + threadIdx.x;
    if (i < CHW) {
        float v = vis[i];
        __nv_bfloat16 h = __float2bfloat16(v);
        g_vs[i] = h;
        g_vs[(size_t)CHW + i] = __float2bfloat16(v - __bfloat162float(h));
    } else {
        int k = i - CHW;
        if (k < 512 * 512) {
            int o = k >> 9, ci = k & 511;
            float v = mw[o * 812 + ci];
            __nv_bfloat16 h = __float2bfloat16(v);
            g_mwsp[k] = h;
            g_mwsp[262144 + k] = __float2bfloat16(v - __bfloat162float(h));
        }
    }
}

// ---------------------------------------------------------------------------
// Plain input transform (for the initial V-plane): src[ci][64][64] -> V splits
// ---------------------------------------------------------------------------
__global__ void wg_itrans_kernel(const float* __restrict__ src,
                                 __nv_bfloat16* __restrict__ V) {
    __shared__ float psm[66][67];
    int ci = blockIdx.x, tid = threadIdx.x;
    const float* sp = src + (size_t)ci * HW;
    for (int i = tid; i < 66 * 67; i += 256) (&psm[0][0])[i] = 0.f;
    __syncthreads();
    for (int i = tid; i < 4096; i += 256)
        psm[(i >> 6) + 1][(i & 63) + 1] = sp[i];
    __syncthreads();
    fwd_write(psm, V, ci, tid);
}

// ---------------------------------------------------------------------------
// FUSED gather (with on-the-fly R inverse transform) + dual forward transform.
// Per-ci block, internal nodes only. Writes cs plane + V0 (cs) + V1 (rh).
// ---------------------------------------------------------------------------
__global__ void gather_itrans_kernel(int n, const float* __restrict__ rb,
                                     __nv_bfloat16* __restrict__ V0,
                                     __nv_bfloat16* __restrict__ V1) {
    int cnt = g_childcount[n];
    if (cnt == 0) return;
    __shared__ float csm[66][67];
    __shared__ float rsm[66][67];
    int ci = blockIdx.x, tid = threadIdx.x;
    for (int i = tid; i < 66 * 67; i += 256) {
        (&csm[0][0])[i] = 0.f;
        (&rsm[0][0])[i] = 0.f;
    }
    __syncthreads();
    float tv[9];
#pragma unroll
    for (int k = 0; k < 9; k++)
        tv[k] = g_t[((0 * NND + n) * 9 + k) * CHN + ci];
    float rbc = rb[ci];
    int ty = tid >> 4, tx = tid & 15;
    const float* Gr = g_buf + 1 * CHW + (size_t)ci * HW;
    float base16[4][4];
#pragma unroll
    for (int i = 0; i < 4; i++)
#pragma unroll
        for (int j = 0; j < 4; j++) {
            int y = 4 * ty + i, x = 4 * tx + j;
            int ky0 = (y == 0), ky1 = 2 - (y == HH - 1);
            int kx0 = (x == 0), kx1 = 2 - (x == WW - 1);
            float cr = 0.f;
            for (int ky = ky0; ky <= ky1; ky++)
                for (int kx = kx0; kx <= kx1; kx++)
                    cr += tv[ky * 3 + kx];
            base16[i][j] = Gr[y * WW + x] + rbc + cr;
        }
    float cs16[4][4], rh16[4][4];
#pragma unroll
    for (int i = 0; i < 4; i++)
#pragma unroll
        for (int j = 0; j < 4; j++) { cs16[i][j] = 0.f; rh16[i][j] = 0.f; }
    for (int c0 = 0; c0 < cnt; c0++) {
        int k = g_child[n * NND + c0];
        float r16[4][4];
        inv_read(g_mr + (size_t)k * M_STRIDE, ci, tid, r16);
        const float* hp = g_buf + (size_t)(8 + k) * CHW + (size_t)ci * HW;
#pragma unroll
        for (int i = 0; i < 4; i++) {
            float4 hv4 = *reinterpret_cast<const float4*>(
                hp + (4 * ty + i) * WW + 4 * tx);
            float hv[4] = {hv4.x, hv4.y, hv4.z, hv4.w};
#pragma unroll
            for (int j = 0; j < 4; j++) {
                float rr = sigm(base16[i][j] + r16[i][j]);
                cs16[i][j] += hv[j];
                rh16[i][j] += rr * hv[j];
            }
        }
    }
    float* csout = g_buf + 4 * CHW + (size_t)ci * HW;
#pragma unroll
    for (int i = 0; i < 4; i++) {
        int y = 4 * ty + i;
        *reinterpret_cast<float4*>(csout + y * WW + 4 * tx) =
            make_float4(cs16[i][0], cs16[i][1], cs16[i][2], cs16[i][3]);
#pragma unroll
        for (int j = 0; j < 4; j++) {
            csm[y + 1][4 * tx + j + 1] = cs16[i][j];
            rsm[y + 1][4 * tx + j + 1] = rh16[i][j];
        }
    }
    __syncthreads();
    fwd_write(csm, V0, ci, tid);
    fwd_write(rsm, V1, ci, tid);
}

// ---------------------------------------------------------------------------
// FUSED inverse(U,O) + combine + forward transform of h (all nodes).
// Per-channel block. Root (n==0): writes out, no transform.
// ---------------------------------------------------------------------------
__global__ void inv_combine_kernel(int n, const float* __restrict__ ub,
                                   const float* __restrict__ ob,
                                   float* __restrict__ outroot,
                                   __nv_bfloat16* __restrict__ V2) {
    __shared__ float hsm[66][67];
    int c = blockIdx.x, tid = threadIdx.x;
    bool haskids = g_childcount[n] > 0;
    for (int i = tid; i < 66 * 67; i += 256) (&hsm[0][0])[i] = 0.f;
    __syncthreads();
    int t = tid, ty = t >> 4, tx = t & 15;
    float u16[4][4], o16[4][4];
    if (haskids) {
        inv_read(g_m, c, t, u16);
        inv_read(g_m + M_STRIDE, c, t, o16);
    }
    float tu9[9], to9[9];
#pragma unroll
    for (int k = 0; k < 9; k++) {
        tu9[k] = g_t[((1 * NND + n) * 9 + k) * CHN + c];
        to9[k] = g_t[((2 * NND + n) * 9 + k) * CHN + c];
    }
    float ubc = ub[c], obc = ob[c];
    const float* Gu = g_buf + 2 * CHW + (size_t)c * HW;
    const float* Go = g_buf + 3 * CHW + (size_t)c * HW;
    const float* CS = g_buf + 4 * CHW + (size_t)c * HW;
    float* hpl = (n == 0) ? (outroot + (size_t)c * HW)
                          : (g_buf + (size_t)(8 + n) * CHW + (size_t)c * HW);
#pragma unroll
    for (int i = 0; i < 4; i++) {
#pragma unroll
        for (int j = 0; j < 4; j++) {
            int y = 4 * ty + i, x = 4 * tx + j;
            int p = y * WW + x;
            int ky0 = (y == 0), ky1 = 2 - (y == HH - 1);
            int kx0 = (x == 0), kx1 = 2 - (x == WW - 1);
            float cu = 0.f, co = 0.f;
            for (int ky = ky0; ky <= ky1; ky++)
                for (int kx = kx0; kx <= kx1; kx++) {
                    cu += tu9[ky * 3 + kx];
                    co += to9[ky * 3 + kx];
                }
            float uacc = haskids ? u16[i][j] : 0.f;
            float oacc = haskids ? o16[i][j] : 0.f;
            float cs   = haskids ? CS[p] : 0.f;
            float z  = sigm(Gu[p] + ubc + cu + uacc);
            float ri = tanhf(Go[p] + obc + co + oacc);
            float h = (1.f - z) * ri + z * cs;
            hpl[p] = h;
            hsm[y + 1][x + 1] = h;
        }
    }
    if (n > 0) {
        __syncthreads();
        fwd_write(hsm, V2, c, t);
    }
}

// ---------------------------------------------------------------------------
// Winograd GEMM: per j, M_j[co][tile] = U_j[co][ci] * V_j[ci][tile]
// bf16 3-split, fp32 accum. K=512 -> 24 stages of 64.
// CTA 128co x 128tile, 4 warps (2m x 2n). grid (2, 4, 36*nconv).
// ONE __syncthreads per stage (3-slot pipeline makes the trailing one redundant).
// ---------------------------------------------------------------------------
#define WG_SMEM 98304   // 3 x (A 16KB + B 16KB)

__device__ __forceinline__ void wg_issue_stage(
    int s, uint32_t sA, int tid, int tileB, int coB, int part, int j,
    const __nv_bfloat16* V) {
    int s3 = s >> 3;
    int cb = (s & 7) << 6;
    int wsplit = (s3 == 1) ? 1 : 0;
    int xsplit = (s3 == 2) ? 1 : 0;
    const __nv_bfloat16* Abase =
        g_uw + ((((size_t)(part * 2 + wsplit) * NJ + j) * 512 + coB) << 9) + cb;
    const __nv_bfloat16* Bbase =
        V + (((size_t)(xsplit * NJ + j) * 512 + cb) * NT2) + tileB;
    uint32_t slot = sA + (s % 3) * 32768;
#pragma unroll
    for (int it = 0; it < 8; it++) {
        int i = tid + it * 128;
        int o = i >> 3, q = i & 7;
        cp16(slot + SWZ(o * 128 + q * 16), Abase + ((size_t)o << 9) + q * 8);
    }
#pragma unroll
    for (int it = 0; it < 8; it++) {
        int i = tid + it * 128;
        int k = i >> 4, cc = i & 15;
        cp16(slot + 16384 + k * 256 + ((cc ^ (k & 7)) << 4),
             Bbase + (size_t)k * NT2 + cc * 8);
    }
    asm volatile("cp.async.commit_group;" ::: "memory");
}

__global__ __launch_bounds__(128)
void wg_gemm_kernel(const __nv_bfloat16* __restrict__ V0, int p0,
                    const __nv_bfloat16* __restrict__ V1, int p1,
                    const __nv_bfloat16* __restrict__ V2, int p2,
                    float* __restrict__ M0, float* __restrict__ M1,
                    float* __restrict__ M2, int flag_n) {
    if (flag_n >= 0 && g_childcount[flag_n] == 0) return;
    extern __shared__ char smem[];
    uint32_t sA = smem_u32(smem);
    int which = blockIdx.z / NJ;
    int j = blockIdx.z - which * NJ;
    const __nv_bfloat16* V = (which == 0) ? V0 : (which == 1) ? V1 : V2;
    int part = (which == 0) ? p0 : (which == 1) ? p1 : p2;
    float* M = (which == 0) ? M0 : (which == 1) ? M1 : M2;

    int tid = threadIdx.x;
    int wid = tid >> 5, lane = tid & 31;
    int tileB = blockIdx.x * 128;
    int coB   = blockIdx.y * 128;
    int wm = wid >> 1;
    int wn = wid & 1;

    float acc[4][8][4];
#pragma unroll
    for (int a = 0; a < 4; a++)
#pragma unroll
        for (int b = 0; b < 8; b++)
#pragma unroll
            for (int c = 0; c < 4; c++) acc[a][b][c] = 0.f;

    wg_issue_stage(0, sA, tid, tileB, coB, part, j, V);
    wg_issue_stage(1, sA, tid, tileB, coB, part, j, V);

    for (int s = 0; s < 24; s++) {
        asm volatile("cp.async.wait_group 1;" ::: "memory");
        __syncthreads();
        if (s + 2 < 24)
            wg_issue_stage(s + 2, sA, tid, tileB, coB, part, j, V);
        uint32_t Ab = sA + (s % 3) * 32768;
        uint32_t Bb = Ab + 16384;
#pragma unroll
        for (int ks = 0; ks < 4; ks++) {
            uint32_t afr[4][4];
#pragma unroll
            for (int mi = 0; mi < 4; mi++) {
                int row = wm * 64 + mi * 16 + (lane & 15);
                int k16 = ks * 2 + (lane >> 4);
                ldm4(afr[mi], Ab + SWZ(row * 128 + k16 * 16));
            }
            uint32_t bfr[4][4];
#pragma unroll
            for (int ng = 0; ng < 4; ng++) {
                int krow = ks * 16 + (lane & 7) + (((lane >> 3) & 1) << 3);
                int cc   = ((wn * 64 + ng * 16) >> 3) + (lane >> 4);
                ldm4t(bfr[ng], Bb + krow * 256 + ((cc ^ (krow & 7)) << 4));
            }
#pragma unroll
            for (int mi = 0; mi < 4; mi++)
#pragma unroll
                for (int ng = 0; ng < 4; ng++) {
                    mma_bf(acc[mi][ng * 2 + 0], afr[mi], bfr[ng][0], bfr[ng][1]);
                    mma_bf(acc[mi][ng * 2 + 1], afr[mi], bfr[ng][2], bfr[ng][3]);
                }
        }
    }

#pragma unroll
    for (int mi = 0; mi < 4; mi++) {
        int row0 = coB + wm * 64 + mi * 16 + (lane >> 2);
        float* mp0 = M + ((size_t)j * 512 + row0) * NT2 + tileB;
#pragma unroll
        for (int nj = 0; nj < 8; nj++) {
            int col = wn * 64 + nj * 8 + (lane & 3) * 2;
            *reinterpret_cast<float2*>(mp0 + col) =
                make_float2(acc[mi][nj][0], acc[mi][nj][1]);
            *reinterpret_cast<float2*>(mp0 + 8 * NT2 + col) =
                make_float2(acc[mi][nj][2], acc[mi][nj][3]);
        }
    }
}

// ---------------------------------------------------------------------------
// mconv 1x1 GEMM via bf16 3-split mma: out[co][px] = mw[:, :512] @ vis
// ---------------------------------------------------------------------------
__device__ __forceinline__ void mc_issue_stage(int s, uint32_t sA, int tid,
                                               int pxB, int coB) {
    int s3 = s >> 3;
    int cb = (s & 7) << 6;
    int wsplit = (s3 == 1) ? 1 : 0;
    int xsplit = (s3 == 2) ? 1 : 0;
    const __nv_bfloat16* Abase = g_mwsp + (size_t)wsplit * 262144 + (coB << 9) + cb;
    const __nv_bfloat16* Bbase = g_vs + (size_t)xsplit * CHW + (size_t)cb * HW + pxB;
    uint32_t slot = sA + (s % 3) * 32768;
#pragma unroll
    for (int it = 0; it < 8; it++) {
        int i = tid + it * 128;
        int o = i >> 3, q = i & 7;
        cp16(slot + SWZ(o * 128 + q * 16), Abase + ((size_t)o << 9) + q * 8);
    }
#pragma unroll
    for (int it = 0; it < 8; it++) {
        int i = tid + it * 128;
        int k = i >> 4, cc = i & 15;
        cp16(slot + 16384 + k * 256 + ((cc ^ (k & 7)) << 4),
             Bbase + (size_t)k * HW + cc * 8);
    }
    asm volatile("cp.async.commit_group;" ::: "memory");
}

__global__ __launch_bounds__(128)
void mc_gemm_kernel(float* __restrict__ out) {
    extern __shared__ char smem[];
    uint32_t sA = smem_u32(smem);
    int tid = threadIdx.x;
    int wid = tid >> 5, lane = tid & 31;
    int pxB = blockIdx.x * 128;
    int coB = blockIdx.y * 128;
    int wm = wid >> 1;
    int wn = wid & 1;

    float acc[4][8][4];
#pragma unroll
    for (int a = 0; a < 4; a++)
#pragma unroll
        for (int b = 0; b < 8; b++)
#pragma unroll
            for (int c = 0; c < 4; c++) acc[a][b][c] = 0.f;

    mc_issue_stage(0, sA, tid, pxB, coB);
    mc_issue_stage(1, sA, tid, pxB, coB);

    for (int s = 0; s < 24; s++) {
        asm volatile("cp.async.wait_group 1;" ::: "memory");
        __syncthreads();
        if (s + 2 < 24)
            mc_issue_stage(s + 2, sA, tid, pxB, coB);
        uint32_t Ab = sA + (s % 3) * 32768;
        uint32_t Bb = Ab + 16384;
#pragma unroll
        for (int ks = 0; ks < 4; ks++) {
            uint32_t afr[4][4];
#pragma unroll
            for (int mi = 0; mi < 4; mi++) {
                int row = wm * 64 + mi * 16 + (lane & 15);
                int k16 = ks * 2 + (lane >> 4);
                ldm4(afr[mi], Ab + SWZ(row * 128 + k16 * 16));
            }
            uint32_t bfr[4][4];
#pragma unroll
            for (int ng = 0; ng < 4; ng++) {
                int krow = ks * 16 + (lane & 7) + (((lane >> 3) & 1) << 3);
                int cc   = ((wn * 64 + ng * 16) >> 3) + (lane >> 4);
                ldm4t(bfr[ng], Bb + krow * 256 + ((cc ^ (krow & 7)) << 4));
            }
#pragma unroll
            for (int mi = 0; mi < 4; mi++)
#pragma unroll
                for (int ng = 0; ng < 4; ng++) {
                    mma_bf(acc[mi][ng * 2 + 0], afr[mi], bfr[ng][0], bfr[ng][1]);
                    mma_bf(acc[mi][ng * 2 + 1], afr[mi], bfr[ng][2], bfr[ng][3]);
                }
        }
    }

#pragma unroll
    for (int mi = 0; mi < 4; mi++) {
        int row0 = coB + wm * 64 + mi * 16 + (lane >> 2);
        float* op = out + (size_t)row0 * HW + pxB;
#pragma unroll
        for (int nj = 0; nj < 8; nj++) {
            int col = wn * 64 + nj * 8 + (lane & 3) * 2;
            *reinterpret_cast<float2*>(op + col) =
                make_float2(acc[mi][nj][0], acc[mi][nj][1]);
            *reinterpret_cast<float2*>(op + 8 * HW + col) =
                make_float2(acc[mi][nj][2], acc[mi][nj][3]);
        }
    }
}

// ---------------------------------------------------------------------------
// Plain inverse transform (initial Gr/Gu/Go convs)
// ---------------------------------------------------------------------------
__global__ void wg_inv_kernel(float* __restrict__ D0, float* __restrict__ D1,
                              float* __restrict__ D2) {
    int conv = blockIdx.y;
    const float* M = g_m + (size_t)conv * M_STRIDE;
    float* D = (conv == 0) ? D0 : (conv == 1) ? D1 : D2;
    int e = blockIdx.x * 256 + threadIdx.x;
    int co = e >> 8, t = e & (NT2 - 1);
    float y16[4][4];
    inv_read(M, co, t, y16);
    int ty = t >> 4, tx = t & 15;
    float* op = D + (size_t)co * HW + (4 * ty) * WW + 4 * tx;
#pragma unroll
    for (int i = 0; i < 4; i++)
        *reinterpret_cast<float4*>(op + i * WW) =
            make_float4(y16[i][0], y16[i][1], y16[i][2], y16[i][3]);
}

// ---------------------------------------------------------------------------
extern "C" void kernel_launch(void* const* d_in, const int* in_sizes, int n_in,
                              void* d_out, int out_size) {
    const float* vis  = (const float*)d_in[0];
    const float* lang = (const float*)d_in[1];
    const int*   adj  = (const int*)d_in[2];
    const float* mw   = (const float*)d_in[3];
    const float* mb   = (const float*)d_in[4];
    const float* rw   = (const float*)d_in[5];
    const float* rb   = (const float*)d_in[6];
    const float* uw   = (const float*)d_in[7];
    const float* ub   = (const float*)d_in[8];
    const float* ow   = (const float*)d_in[9];
    const float* ob   = (const float*)d_in[10];
    float* out = (float*)d_out;

    float* buf = nullptr;
    cudaGetSymbolAddress((void**)&buf, g_buf);
    __nv_bfloat16* wv = nullptr;
    cudaGetSymbolAddress((void**)&wv, g_wV);
    float* m = nullptr;
    cudaGetSymbolAddress((void**)&m, g_m);
    float* mr = nullptr;
    cudaGetSymbolAddress((void**)&mr, g_mr);
    __nv_bfloat16* V0 = wv;
    __nv_bfloat16* V1 = wv + VT_STRIDE;
    __nv_bfloat16* V2 = wv + 2 * VT_STRIDE;

    static bool init_done = false;
    if (!init_done) {
        cudaFuncSetAttribute(wg_gemm_kernel,
                             cudaFuncAttributeMaxDynamicSharedMemorySize, WG_SMEM);
        cudaFuncSetAttribute(mc_gemm_kernel,
                             cudaFuncAttributeMaxDynamicSharedMemorySize, WG_SMEM);
        init_done = true;
    }

    dim3 wgrid1(2, 4, NJ);               // winograd gemm, 1 conv
    dim3 wgrid2(2, 4, 2 * NJ);           // 2 convs
    dim3 wgrid3(2, 4, 3 * NJ);           // 3 convs
    dim3 mcg(32, 4);                     // mconv gemm
    dim3 inv3(512, 3);

    prep_kernel<<<1, 32>>>(adj);
    langbias_kernel<<<40, 256>>>(lang, mw, mb);
    tapconst_kernel<<<54, 256>>>(rw, uw, ow);
    wg_wprep_kernel<<<6144, 256>>>(rw, uw, ow);
    mc_split_kernel<<<9216, 256>>>(vis, mw);

    // V-plane = conv1x1(vis, mconv_w[:, :512]) via split-bf16 mma
    mc_gemm_kernel<<<mcg, 128, WG_SMEM>>>(buf);
    wg_itrans_kernel<<<512, 256>>>(buf, V0);

    // shared convs of V (x-part weights of the 3 gates): Gr, Gu, Go
    wg_gemm_kernel<<<wgrid3, 128, WG_SMEM>>>(V0, 0, V0, 2, V0, 4,
                                             m, m + M_STRIDE, m + 2 * M_STRIDE, -1);
    wg_inv_kernel<<<inv3, 256>>>(buf + 1 * CHW, buf + 2 * CHW, buf + 3 * CHW);

    // nodes in decreasing index = valid topological order (parent(i) < i)
    for (int n = NND - 1; n >= 0; n--) {
        if (n < NND - 1) {  // node NND-1 is statically a leaf: skip no-op launches
            // fused gather (+R inverse) + forward transforms of cs, rh (skips on leaf)
            gather_itrans_kernel<<<512, 256>>>(n, rb, V0, V1);
            // U = conv(cs, Wu_h), O = conv(rh, Wo_h) (skips on leaf)
            wg_gemm_kernel<<<wgrid2, 128, WG_SMEM>>>(V0, 3, V1, 5, V1, 5,
                                                     m, m + M_STRIDE,
                                                     m + 2 * M_STRIDE, n);
        }
        // fused inverse(U,O) + combine (+ forward transform of h when n>0)
        inv_combine_kernel<<<512, 256>>>(n, ub, ob, out, V2);
        if (n > 0)  // R[n] (Winograd domain, inverse deferred to parent's gather)
            wg_gemm_kernel<<<wgrid1, 128, WG_SMEM>>>(
                V2, 1, V2, 1, V2, 1,
                mr + (size_t)n * M_STRIDE, nullptr, nullptr, -1);
    }
}

// round 17
// speedup vs baseline: 1.0521x; 1.0301x over previous
#include <cuda_runtime.h>
#include <cuda_bf16.h>
#include <cstdio>
#include <cstdint>

#define NND 20
#define CHN 512
#define HH  64
#define WW  64
#define HW  4096
#define CHW 2097152   // 512*64*64
#define NT2 256       // winograd F(4,3) tiles per plane (16x16)
#define NJ  36        // 6x6 transform coefficients

// Scratch planes: [V:1][Gr,Gu,Go:3][cs:1][-:3][h:20] = 28 planes
__device__ float g_buf[28ll * CHW];
__device__ float g_b[NND * CHN];            // per-node channel bias
__device__ float g_t[3 * NND * 9 * CHN];    // per-gate per-node per-tap const vectors
__device__ int   g_childcount[NND];
__device__ int   g_child[NND * NND];

// Winograd-transformed weights: [part(6)][split(2)][j(36)][o(512)][ci(512)] bf16
// parts: 0=reset_x 1=reset_h 2=update_x 3=update_h 4=output_x 5=output_h
__device__ __nv_bfloat16 g_uw[6ll * 2 * NJ * 512 * 512];
// Winograd-transformed inputs: 3 slots (V0 cs, V1 rh, V2 h), each
// [split(2)][j(36)][ci(512)][tile(256)]
#define VT_SLOT (2ll * NJ * 512 * NT2)
__device__ __nv_bfloat16 g_wV[3ll * VT_SLOT];
// GEMM outputs: [conv(3)][j(36)][co(512)][tile(256)] fp32
// (ALSO reused, reinterpreted as bf16, as 3 extra leaf V slots before the loop)
__device__ float g_m[3ll * NJ * 512 * NT2];
#define M_STRIDE ((size_t)NJ * 512 * NT2)
// Per-node Winograd-domain R-conv results (kept until parent's gather)
__device__ float g_mr[(size_t)NND * NJ * 512 * NT2];
// mconv (1x1) bf16 split operands
__device__ __nv_bfloat16 g_vs[2ll * CHW];          // vis splits [split][ci][px]
__device__ __nv_bfloat16 g_mwsp[2ll * 512 * 512];  // mconv W splits [split][o][ci]

__device__ __forceinline__ float sigm(float v) { return 1.f / (1.f + expf(-v)); }

// ======================= low-level helpers (sm_100-safe) ====================
__device__ __forceinline__ uint32_t smem_u32(const void* p) {
    uint32_t a;
    asm("{ .reg .u64 t; cvta.to.shared.u64 t, %1; cvt.u32.u64 %0, t; }"
        : "=r"(a) : "l"(p));
    return a;
}
__device__ __forceinline__ void cp16(uint32_t dst, const void* src) {
    asm volatile("cp.async.cg.shared.global [%0], [%1], 16;"
        :: "r"(dst), "l"(src) : "memory");
}
__device__ __forceinline__ void ldm4(uint32_t* r, uint32_t addr) {
    asm volatile("ldmatrix.sync.aligned.m8n8.x4.shared.b16 {%0,%1,%2,%3}, [%4];"
        : "=r"(r[0]), "=r"(r[1]), "=r"(r[2]), "=r"(r[3]) : "r"(addr));
}
__device__ __forceinline__ void ldm4t(uint32_t* r, uint32_t addr) {
    asm volatile("ldmatrix.sync.aligned.m8n8.x4.trans.shared.b16 {%0,%1,%2,%3}, [%4];"
        : "=r"(r[0]), "=r"(r[1]), "=r"(r[2]), "=r"(r[3]) : "r"(addr));
}
__device__ __forceinline__ void mma_bf(float* c, const uint32_t* a,
                                       uint32_t b0, uint32_t b1) {
    asm volatile(
        "mma.sync.aligned.m16n8k16.row.col.f32.bf16.bf16.f32 "
        "{%0,%1,%2,%3}, {%4,%5,%6,%7}, {%8,%9}, {%0,%1,%2,%3};"
        : "+f"(c[0]), "+f"(c[1]), "+f"(c[2]), "+f"(c[3])
        : "r"(a[0]), "r"(a[1]), "r"(a[2]), "r"(a[3]), "r"(b0), "r"(b1));
}
#define SWZ(off) ((off) ^ (((off) >> 3) & 0x70))

// leaf V slot selector: y in [0,6) -> g_wV slots 0-2, then g_m reinterpreted
__device__ __forceinline__ __nv_bfloat16* leaf_slot(int y) {
    if (y < 3) return g_wV + (size_t)y * VT_SLOT;
    return reinterpret_cast<__nv_bfloat16*>(g_m) + (size_t)(y - 3) * VT_SLOT;
}

// ---------------------------------------------------------------------------
// Tree prep
// ---------------------------------------------------------------------------
__global__ void prep_kernel(const int* __restrict__ adj) {
    int n = threadIdx.x;
    if (n < NND) {
        int cnt = 0;
        for (int k = 0; k < NND; k++)
            if (adj[n * NND + k] != 0) g_child[n * NND + cnt++] = k;
        g_childcount[n] = cnt;
    }
}

// ---------------------------------------------------------------------------
// b[n][o] = mconv_b[o] + sum_i mconv_w[o, 512+i] * lang[n, i]
// ---------------------------------------------------------------------------
__global__ void langbias_kernel(const float* __restrict__ lang,
                                const float* __restrict__ mw,
                                const float* __restrict__ mb) {
    int idx = blockIdx.x * 256 + threadIdx.x;
    if (idx >= NND * CHN) return;
    int n = idx / CHN, o = idx - n * CHN;
    const float* wp = mw + o * 812 + 512;
    const float* lp = lang + n * 300;
    float acc = mb[o];
    for (int i = 0; i < 300; i++) acc += wp[i] * lp[i];
    g_b[idx] = acc;
}

// ---------------------------------------------------------------------------
// t[g][n][tap][o] = sum_{i<512} Wg_x[o,i,tap] * b[n][i]
// ---------------------------------------------------------------------------
__global__ void tapconst_kernel(const float* __restrict__ rw,
                                const float* __restrict__ uw,
                                const float* __restrict__ ow) {
    __shared__ float bs[NND * CHN];  // 40KB
    int tid = threadIdx.x;
    for (int idx = tid; idx < NND * CHN; idx += 256) bs[idx] = g_b[idx];
    __syncthreads();
    int gidx = blockIdx.x * 256 + tid;
    int o   = gidx & (CHN - 1);
    int tap = (gidx >> 9) % 9;
    int g   = gidx / (CHN * 9);
    const float* w = (g == 0) ? rw : (g == 1) ? uw : ow;
    const float* wp = w + o * 9216 + tap;
    float acc[NND];
#pragma unroll
    for (int n = 0; n < NND; n++) acc[n] = 0.f;
    for (int i = 0; i < CHN; i++) {
        float wv = wp[i * 9];
#pragma unroll
        for (int n = 0; n < NND; n++) acc[n] += wv * bs[n * CHN + i];
    }
#pragma unroll
    for (int n = 0; n < NND; n++)
        g_t[((g * NND + n) * 9 + tap) * CHN + o] = acc[n];
}

// ---------------------------------------------------------------------------
// F(4,3) transform primitives
// ---------------------------------------------------------------------------
__device__ __forceinline__ void gtrans(float v0, float v1, float v2, float* u) {
    u[0] = 0.25f * v0;
    u[1] = -(v0 + v1 + v2) * (1.f / 6.f);
    u[2] = (-v0 + v1 - v2) * (1.f / 6.f);
    u[3] = (v0 + 2.f * v1 + 4.f * v2) * (1.f / 24.f);
    u[4] = (v0 - 2.f * v1 + 4.f * v2) * (1.f / 24.f);
    u[5] = v2;
}
__device__ __forceinline__ void bttrans(const float* v, float* w) {
    w[0] = 4.f * v[0] - 5.f * v[2] + v[4];
    w[1] = -4.f * v[1] - 4.f * v[2] + v[3] + v[4];
    w[2] = 4.f * v[1] - 4.f * v[2] - v[3] + v[4];
    w[3] = -2.f * v[1] - v[2] + 2.f * v[3] + v[4];
    w[4] = 2.f * v[1] - v[2] - 2.f * v[3] + v[4];
    w[5] = 4.f * v[1] - 5.f * v[3] + v[5];
}
__device__ __forceinline__ void attrans(const float* v, float* y) {
    y[0] = v[0] + v[1] + v[2] + v[3] + v[4];
    y[1] = v[1] - v[2] + 2.f * (v[3] - v[4]);
    y[2] = v[1] + v[2] + 4.f * (v[3] + v[4]);
    y[3] = v[1] - v[2] + 8.f * (v[3] - v[4]) + v[5];
}
__device__ __forceinline__ void fwd_write(const float (*psm)[67],
                                          __nv_bfloat16* __restrict__ V,
                                          int ci, int t) {
    int ty = t >> 4, tx = t & 15;
    float d[6][6], c[6][6];
#pragma unroll
    for (int i = 0; i < 6; i++)
#pragma unroll
        for (int j = 0; j < 6; j++)
            d[i][j] = psm[4 * ty + i][4 * tx + j];
#pragma unroll
    for (int j = 0; j < 6; j++) {
        float vin[6], vo[6];
#pragma unroll
        for (int i = 0; i < 6; i++) vin[i] = d[i][j];
        bttrans(vin, vo);
#pragma unroll
        for (int i = 0; i < 6; i++) c[i][j] = vo[i];
    }
#pragma unroll
    for (int i = 0; i < 6; i++) {
        float vo[6];
        bttrans(c[i], vo);
#pragma unroll
        for (int j = 0; j < 6; j++) {
            int j36 = i * 6 + j;
            size_t o = ((size_t)j36 * 512 + ci) * NT2 + t;
            __nv_bfloat16 h = __float2bfloat16(vo[j]);
            V[o] = h;
            V[o + (size_t)NJ * 512 * NT2] =
                __float2bfloat16(vo[j] - __bfloat162float(h));
        }
    }
}
__device__ __forceinline__ void inv_read(const float* __restrict__ M,
                                         int c, int t, float y16[4][4]) {
    float Z[6][6];
#pragma unroll
    for (int i = 0; i < 6; i++)
#pragma unroll
        for (int j = 0; j < 6; j++)
            Z[i][j] = M[((size_t)(i * 6 + j) * 512 + c) * NT2 + t];
    float cc[4][6];
#pragma unroll
    for (int j = 0; j < 6; j++) {
        float vin[6], vo[4];
#pragma unroll
        for (int i = 0; i < 6; i++) vin[i] = Z[i][j];
        attrans(vin, vo);
#pragma unroll
        for (int i = 0; i < 4; i++) cc[i][j] = vo[i];
    }
#pragma unroll
    for (int i = 0; i < 4; i++) attrans(cc[i], y16[i]);
}

// ---------------------------------------------------------------------------
// F(4,3) weight transform: U = G g G^T (6x6), split hi/lo bf16.
// ---------------------------------------------------------------------------
__global__ void wg_wprep_kernel(const float* __restrict__ rw,
                                const float* __restrict__ uw,
                                const float* __restrict__ ow) {
    int idx = blockIdx.x * 256 + threadIdx.x;
    if (idx >= 6 * 512 * 512) return;
    int ci = idx & 511;
    int o  = (idx >> 9) & 511;
    int part = idx >> 18;
    const float* w = (part < 2) ? rw : (part < 4) ? uw : ow;
    int coff = (part & 1) << 9;
    const float* gp = w + (size_t)o * 9216 + (size_t)(coff + ci) * 9;
    float g[9];
#pragma unroll
    for (int k = 0; k < 9; k++) g[k] = gp[k];
    float a[6][3];
#pragma unroll
    for (int j = 0; j < 3; j++) {
        float u[6];
        gtrans(g[j], g[3 + j], g[6 + j], u);
#pragma unroll
        for (int i = 0; i < 6; i++) a[i][j] = u[i];
    }
#pragma unroll
    for (int i = 0; i < 6; i++) {
        float U[6];
        gtrans(a[i][0], a[i][1], a[i][2], U);
#pragma unroll
        for (int j = 0; j < 6; j++) {
            int j36 = i * 6 + j;
            size_t base = ((((size_t)(part * 2) * NJ + j36) * 512 + o) << 9) + ci;
            __nv_bfloat16 h = __float2bfloat16(U[j]);
            g_uw[base] = h;
            g_uw[base + (size_t)NJ * 512 * 512] =
                __float2bfloat16(U[j] - __bfloat162float(h));
        }
    }
}

// ---------------------------------------------------------------------------
// mconv operand splits (vis + weights in one kernel)
// ---------------------------------------------------------------------------
__global__ void mc_split_kernel(const float* __restrict__ vis,
                                const float* __restrict__ mw) {
    int i = blockIdx.x * 256 + threadIdx.x;
    if (i < CHW) {
        float v = vis[i];
        __nv_bfloat16 h = __float2bfloat16(v);
        g_vs[i] = h;
        g_vs[(size_t)CHW + i] = __float2bfloat16(v - __bfloat162float(h));
    } else {
        int k = i - CHW;
        if (k < 512 * 512) {
            int o = k >> 9, ci = k & 511;
            float v = mw[o * 812 + ci];
            __nv_bfloat16 h = __float2bfloat16(v);
            g_mwsp[k] = h;
            g_mwsp[262144 + k] = __float2bfloat16(v - __bfloat162float(h));
        }
    }
}

// ---------------------------------------------------------------------------
// Plain input transform (for the initial V-plane): src[ci][64][64] -> V splits
// ---------------------------------------------------------------------------
__global__ void wg_itrans_kernel(const float* __restrict__ src,
                                 __nv_bfloat16* __restrict__ V) {
    __shared__ float psm[66][67];
    int ci = blockIdx.x, tid = threadIdx.x;
    const float* sp = src + (size_t)ci * HW;
    for (int i = tid; i < 66 * 67; i += 256) (&psm[0][0])[i] = 0.f;
    __syncthreads();
    for (int i = tid; i < 4096; i += 256)
        psm[(i >> 6) + 1][(i & 63) + 1] = sp[i];
    __syncthreads();
    fwd_write(psm, V, ci, tid);
}

// ---------------------------------------------------------------------------
// BATCHED leaf combine: nodes nbase..nbase+5; leaves only.
// h = (1-z)*tanh(Go + co + ob)  [cs = uacc = oacc = 0], then fwd transform
// into leaf slot blockIdx.y. grid (512, 6).
// ---------------------------------------------------------------------------
__global__ void leaf_combine_kernel(int nbase, const float* __restrict__ ub,
                                    const float* __restrict__ ob) {
    int n = nbase + blockIdx.y;
    if (n >= NND || g_childcount[n] != 0) return;
    __shared__ float hsm[66][67];
    int c = blockIdx.x, tid = threadIdx.x;
    for (int i = tid; i < 66 * 67; i += 256) (&hsm[0][0])[i] = 0.f;
    __syncthreads();
    int t = tid, ty = t >> 4, tx = t & 15;
    float tu9[9], to9[9];
#pragma unroll
    for (int k = 0; k < 9; k++) {
        tu9[k] = g_t[((1 * NND + n) * 9 + k) * CHN + c];
        to9[k] = g_t[((2 * NND + n) * 9 + k) * CHN + c];
    }
    float ubc = ub[c], obc = ob[c];
    const float* Gu = g_buf + 2 * CHW + (size_t)c * HW;
    const float* Go = g_buf + 3 * CHW + (size_t)c * HW;
    float* hpl = g_buf + (size_t)(8 + n) * CHW + (size_t)c * HW;
#pragma unroll
    for (int i = 0; i < 4; i++)
#pragma unroll
        for (int j = 0; j < 4; j++) {
            int y = 4 * ty + i, x = 4 * tx + j;
            int p = y * WW + x;
            int ky0 = (y == 0), ky1 = 2 - (y == HH - 1);
            int kx0 = (x == 0), kx1 = 2 - (x == WW - 1);
            float cu = 0.f, co = 0.f;
            for (int ky = ky0; ky <= ky1; ky++)
                for (int kx = kx0; kx <= kx1; kx++) {
                    cu += tu9[ky * 3 + kx];
                    co += to9[ky * 3 + kx];
                }
            float z  = sigm(Gu[p] + ubc + cu);
            float ri = tanhf(Go[p] + obc + co);
            float h = (1.f - z) * ri;
            hpl[p] = h;
            hsm[y + 1][x + 1] = h;
        }
    __syncthreads();
    fwd_write(hsm, leaf_slot(blockIdx.y), c, t);
}

// ---------------------------------------------------------------------------
// FUSED gather (with on-the-fly R inverse transform) + dual forward transform.
// Per-ci block, internal nodes only. Writes cs plane + V0 (cs) + V1 (rh).
// ---------------------------------------------------------------------------
__global__ void gather_itrans_kernel(int n, const float* __restrict__ rb,
                                     __nv_bfloat16* __restrict__ V0,
                                     __nv_bfloat16* __restrict__ V1) {
    int cnt = g_childcount[n];
    if (cnt == 0) return;
    __shared__ float csm[66][67];
    __shared__ float rsm[66][67];
    int ci = blockIdx.x, tid = threadIdx.x;
    for (int i = tid; i < 66 * 67; i += 256) {
        (&csm[0][0])[i] = 0.f;
        (&rsm[0][0])[i] = 0.f;
    }
    __syncthreads();
    float tv[9];
#pragma unroll
    for (int k = 0; k < 9; k++)
        tv[k] = g_t[((0 * NND + n) * 9 + k) * CHN + ci];
    float rbc = rb[ci];
    int ty = tid >> 4, tx = tid & 15;
    const float* Gr = g_buf + 1 * CHW + (size_t)ci * HW;
    float base16[4][4];
#pragma unroll
    for (int i = 0; i < 4; i++)
#pragma unroll
        for (int j = 0; j < 4; j++) {
            int y = 4 * ty + i, x = 4 * tx + j;
            int ky0 = (y == 0), ky1 = 2 - (y == HH - 1);
            int kx0 = (x == 0), kx1 = 2 - (x == WW - 1);
            float cr = 0.f;
            for (int ky = ky0; ky <= ky1; ky++)
                for (int kx = kx0; kx <= kx1; kx++)
                    cr += tv[ky * 3 + kx];
            base16[i][j] = Gr[y * WW + x] + rbc + cr;
        }
    float cs16[4][4], rh16[4][4];
#pragma unroll
    for (int i = 0; i < 4; i++)
#pragma unroll
        for (int j = 0; j < 4; j++) { cs16[i][j] = 0.f; rh16[i][j] = 0.f; }
    for (int c0 = 0; c0 < cnt; c0++) {
        int k = g_child[n * NND + c0];
        float r16[4][4];
        inv_read(g_mr + (size_t)k * M_STRIDE, ci, tid, r16);
        const float* hp = g_buf + (size_t)(8 + k) * CHW + (size_t)ci * HW;
#pragma unroll
        for (int i = 0; i < 4; i++) {
            float4 hv4 = *reinterpret_cast<const float4*>(
                hp + (4 * ty + i) * WW + 4 * tx);
            float hv[4] = {hv4.x, hv4.y, hv4.z, hv4.w};
#pragma unroll
            for (int j = 0; j < 4; j++) {
                float rr = sigm(base16[i][j] + r16[i][j]);
                cs16[i][j] += hv[j];
                rh16[i][j] += rr * hv[j];
            }
        }
    }
    float* csout = g_buf + 4 * CHW + (size_t)ci * HW;
#pragma unroll
    for (int i = 0; i < 4; i++) {
        int y = 4 * ty + i;
        *reinterpret_cast<float4*>(csout + y * WW + 4 * tx) =
            make_float4(cs16[i][0], cs16[i][1], cs16[i][2], cs16[i][3]);
#pragma unroll
        for (int j = 0; j < 4; j++) {
            csm[y + 1][4 * tx + j + 1] = cs16[i][j];
            rsm[y + 1][4 * tx + j + 1] = rh16[i][j];
        }
    }
    __syncthreads();
    fwd_write(csm, V0, ci, tid);
    fwd_write(rsm, V1, ci, tid);
}

// ---------------------------------------------------------------------------
// FUSED inverse(U,O) + combine + forward transform of h.
// Internal nodes only (leaves handled upfront). Root writes out, no transform.
// ---------------------------------------------------------------------------
__global__ void inv_combine_kernel(int n, const float* __restrict__ ub,
                                   const float* __restrict__ ob,
                                   float* __restrict__ outroot,
                                   __nv_bfloat16* __restrict__ V2) {
    if (n > 0 && g_childcount[n] == 0) return;   // leaf handled upfront
    __shared__ float hsm[66][67];
    int c = blockIdx.x, tid = threadIdx.x;
    for (int i = tid; i < 66 * 67; i += 256) (&hsm[0][0])[i] = 0.f;
    __syncthreads();
    int t = tid, ty = t >> 4, tx = t & 15;
    float u16[4][4], o16[4][4];
    inv_read(g_m, c, t, u16);
    inv_read(g_m + M_STRIDE, c, t, o16);
    float tu9[9], to9[9];
#pragma unroll
    for (int k = 0; k < 9; k++) {
        tu9[k] = g_t[((1 * NND + n) * 9 + k) * CHN + c];
        to9[k] = g_t[((2 * NND + n) * 9 + k) * CHN + c];
    }
    float ubc = ub[c], obc = ob[c];
    const float* Gu = g_buf + 2 * CHW + (size_t)c * HW;
    const float* Go = g_buf + 3 * CHW + (size_t)c * HW;
    const float* CS = g_buf + 4 * CHW + (size_t)c * HW;
    float* hpl = (n == 0) ? (outroot + (size_t)c * HW)
                          : (g_buf + (size_t)(8 + n) * CHW + (size_t)c * HW);
#pragma unroll
    for (int i = 0; i < 4; i++)
#pragma unroll
        for (int j = 0; j < 4; j++) {
            int y = 4 * ty + i, x = 4 * tx + j;
            int p = y * WW + x;
            int ky0 = (y == 0), ky1 = 2 - (y == HH - 1);
            int kx0 = (x == 0), kx1 = 2 - (x == WW - 1);
            float cu = 0.f, co = 0.f;
            for (int ky = ky0; ky <= ky1; ky++)
                for (int kx = kx0; kx <= kx1; kx++) {
                    cu += tu9[ky * 3 + kx];
                    co += to9[ky * 3 + kx];
                }
            float z  = sigm(Gu[p] + ubc + cu + u16[i][j]);
            float ri = tanhf(Go[p] + obc + co + o16[i][j]);
            float h = (1.f - z) * ri + z * CS[p];
            hpl[p] = h;
            hsm[y + 1][x + 1] = h;
        }
    if (n > 0) {
        __syncthreads();
        fwd_write(hsm, V2, c, t);
    }
}

// ---------------------------------------------------------------------------
// Winograd GEMM core. bf16 3-split, fp32 accum. K=512 -> 24 stages of 64.
// CTA 128co x 128tile, 4 warps (2m x 2n). ONE __syncthreads per stage.
// ---------------------------------------------------------------------------
#define WG_SMEM 98304   // 3 x (A 16KB + B 16KB)

__device__ __forceinline__ void wg_issue_stage(
    int s, uint32_t sA, int tid, int tileB, int coB, int part, int j,
    const __nv_bfloat16* V) {
    int s3 = s >> 3;
    int cb = (s & 7) << 6;
    int wsplit = (s3 == 1) ? 1 : 0;
    int xsplit = (s3 == 2) ? 1 : 0;
    const __nv_bfloat16* Abase =
        g_uw + ((((size_t)(part * 2 + wsplit) * NJ + j) * 512 + coB) << 9) + cb;
    const __nv_bfloat16* Bbase =
        V + (((size_t)(xsplit * NJ + j) * 512 + cb) * NT2) + tileB;
    uint32_t slot = sA + (s % 3) * 32768;
#pragma unroll
    for (int it = 0; it < 8; it++) {
        int i = tid + it * 128;
        int o = i >> 3, q = i & 7;
        cp16(slot + SWZ(o * 128 + q * 16), Abase + ((size_t)o << 9) + q * 8);
    }
#pragma unroll
    for (int it = 0; it < 8; it++) {
        int i = tid + it * 128;
        int k = i >> 4, cc = i & 15;
        cp16(slot + 16384 + k * 256 + ((cc ^ (k & 7)) << 4),
             Bbase + (size_t)k * NT2 + cc * 8);
    }
    asm volatile("cp.async.commit_group;" ::: "memory");
}

__device__ __forceinline__ void wg_gemm_body(
    const __nv_bfloat16* __restrict__ V, int part, float* __restrict__ M,
    int j, char* smem) {
    uint32_t sA = smem_u32(smem);
    int tid = threadIdx.x;
    int wid = tid >> 5, lane = tid & 31;
    int tileB = blockIdx.x * 128;
    int coB   = blockIdx.y * 128;
    int wm = wid >> 1;
    int wn = wid & 1;

    float acc[4][8][4];
#pragma unroll
    for (int a = 0; a < 4; a++)
#pragma unroll
        for (int b = 0; b < 8; b++)
#pragma unroll
            for (int c = 0; c < 4; c++) acc[a][b][c] = 0.f;

    wg_issue_stage(0, sA, tid, tileB, coB, part, j, V);
    wg_issue_stage(1, sA, tid, tileB, coB, part, j, V);

    for (int s = 0; s < 24; s++) {
        asm volatile("cp.async.wait_group 1;" ::: "memory");
        __syncthreads();
        if (s + 2 < 24)
            wg_issue_stage(s + 2, sA, tid, tileB, coB, part, j, V);
        uint32_t Ab = sA + (s % 3) * 32768;
        uint32_t Bb = Ab + 16384;
#pragma unroll
        for (int ks = 0; ks < 4; ks++) {
            uint32_t afr[4][4];
#pragma unroll
            for (int mi = 0; mi < 4; mi++) {
                int row = wm * 64 + mi * 16 + (lane & 15);
                int k16 = ks * 2 + (lane >> 4);
                ldm4(afr[mi], Ab + SWZ(row * 128 + k16 * 16));
            }
            uint32_t bfr[4][4];
#pragma unroll
            for (int ng = 0; ng < 4; ng++) {
                int krow = ks * 16 + (lane & 7) + (((lane >> 3) & 1) << 3);
                int cc   = ((wn * 64 + ng * 16) >> 3) + (lane >> 4);
                ldm4t(bfr[ng], Bb + krow * 256 + ((cc ^ (krow & 7)) << 4));
            }
#pragma unroll
            for (int mi = 0; mi < 4; mi++)
#pragma unroll
                for (int ng = 0; ng < 4; ng++) {
                    mma_bf(acc[mi][ng * 2 + 0], afr[mi], bfr[ng][0], bfr[ng][1]);
                    mma_bf(acc[mi][ng * 2 + 1], afr[mi], bfr[ng][2], bfr[ng][3]);
                }
        }
    }

#pragma unroll
    for (int mi = 0; mi < 4; mi++) {
        int row0 = coB + wm * 64 + mi * 16 + (lane >> 2);
        float* mp0 = M + ((size_t)j * 512 + row0) * NT2 + tileB;
#pragma unroll
        for (int nj = 0; nj < 8; nj++) {
            int col = wn * 64 + nj * 8 + (lane & 3) * 2;
            *reinterpret_cast<float2*>(mp0 + col) =
                make_float2(acc[mi][nj][0], acc[mi][nj][1]);
            *reinterpret_cast<float2*>(mp0 + 8 * NT2 + col) =
                make_float2(acc[mi][nj][2], acc[mi][nj][3]);
        }
    }
}

// up to 3 convs per launch; flag_n >= 0: run only if node internal
__global__ __launch_bounds__(128)
void wg_gemm_kernel(const __nv_bfloat16* __restrict__ V0, int p0,
                    const __nv_bfloat16* __restrict__ V1, int p1,
                    const __nv_bfloat16* __restrict__ V2, int p2,
                    float* __restrict__ M0, float* __restrict__ M1,
                    float* __restrict__ M2, int flag_n) {
    if (flag_n >= 0 && g_childcount[flag_n] == 0) return;
    extern __shared__ char smem[];
    int which = blockIdx.z / NJ;
    int j = blockIdx.z - which * NJ;
    const __nv_bfloat16* V = (which == 0) ? V0 : (which == 1) ? V1 : V2;
    int part = (which == 0) ? p0 : (which == 1) ? p1 : p2;
    float* M = (which == 0) ? M0 : (which == 1) ? M1 : M2;
    wg_gemm_body(V, part, M, j, smem);
}

// batched leaf R GEMM: nodes nbase..nbase+5 (leaves only), V from leaf_slot
__global__ __launch_bounds__(128)
void wg_gemm_leaf_kernel(int nbase) {
    int y = blockIdx.z / NJ;
    int node = nbase + y;
    if (node >= NND || g_childcount[node] != 0) return;
    int j = blockIdx.z - y * NJ;
    extern __shared__ char smem[];
    wg_gemm_body(leaf_slot(y), 1, g_mr + (size_t)node * M_STRIDE, j, smem);
}

// ---------------------------------------------------------------------------
// mconv 1x1 GEMM via bf16 3-split mma: out[co][px] = mw[:, :512] @ vis
// ---------------------------------------------------------------------------
__device__ __forceinline__ void mc_issue_stage(int s, uint32_t sA, int tid,
                                               int pxB, int coB) {
    int s3 = s >> 3;
    int cb = (s & 7) << 6;
    int wsplit = (s3 == 1) ? 1 : 0;
    int xsplit = (s3 == 2) ? 1 : 0;
    const __nv_bfloat16* Abase = g_mwsp + (size_t)wsplit * 262144 + (coB << 9) + cb;
    const __nv_bfloat16* Bbase = g_vs + (size_t)xsplit * CHW + (size_t)cb * HW + pxB;
    uint32_t slot = sA + (s % 3) * 32768;
#pragma unroll
    for (int it = 0; it < 8; it++) {
        int i = tid + it * 128;
        int o = i >> 3, q = i & 7;
        cp16(slot + SWZ(o * 128 + q * 16), Abase + ((size_t)o << 9) + q * 8);
    }
#pragma unroll
    for (int it = 0; it < 8; it++) {
        int i = tid + it * 128;
        int k = i >> 4, cc = i & 15;
        cp16(slot + 16384 + k * 256 + ((cc ^ (k & 7)) << 4),
             Bbase + (size_t)k * HW + cc * 8);
    }
    asm volatile("cp.async.commit_group;" ::: "memory");
}

__global__ __launch_bounds__(128)
void mc_gemm_kernel(float* __restrict__ out) {
    extern __shared__ char smem[];
    uint32_t sA = smem_u32(smem);
    int tid = threadIdx.x;
    int wid = tid >> 5, lane = tid & 31;
    int pxB = blockIdx.x * 128;
    int coB = blockIdx.y * 128;
    int wm = wid >> 1;
    int wn = wid & 1;

    float acc[4][8][4];
#pragma unroll
    for (int a = 0; a < 4; a++)
#pragma unroll
        for (int b = 0; b < 8; b++)
#pragma unroll
            for (int c = 0; c < 4; c++) acc[a][b][c] = 0.f;

    mc_issue_stage(0, sA, tid, pxB, coB);
    mc_issue_stage(1, sA, tid, pxB, coB);

    for (int s = 0; s < 24; s++) {
        asm volatile("cp.async.wait_group 1;" ::: "memory");
        __syncthreads();
        if (s + 2 < 24)
            mc_issue_stage(s + 2, sA, tid, pxB, coB);
        uint32_t Ab = sA + (s % 3) * 32768;
        uint32_t Bb = Ab + 16384;
#pragma unroll
        for (int ks = 0; ks < 4; ks++) {
            uint32_t afr[4][4];
#pragma unroll
            for (int mi = 0; mi < 4; mi++) {
                int row = wm * 64 + mi * 16 + (lane & 15);
                int k16 = ks * 2 + (lane >> 4);
                ldm4(afr[mi], Ab + SWZ(row * 128 + k16 * 16));
            }
            uint32_t bfr[4][4];
#pragma unroll
            for (int ng = 0; ng < 4; ng++) {
                int krow = ks * 16 + (lane & 7) + (((lane >> 3) & 1) << 3);
                int cc   = ((wn * 64 + ng * 16) >> 3) + (lane >> 4);
                ldm4t(bfr[ng], Bb + krow * 256 + ((cc ^ (krow & 7)) << 4));
            }
#pragma unroll
            for (int mi = 0; mi < 4; mi++)
#pragma unroll
                for (int ng = 0; ng < 4; ng++) {
                    mma_bf(acc[mi][ng * 2 + 0], afr[mi], bfr[ng][0], bfr[ng][1]);
                    mma_bf(acc[mi][ng * 2 + 1], afr[mi], bfr[ng][2], bfr[ng][3]);
                }
        }
    }

#pragma unroll
    for (int mi = 0; mi < 4; mi++) {
        int row0 = coB + wm * 64 + mi * 16 + (lane >> 2);
        float* op = out + (size_t)row0 * HW + pxB;
#pragma unroll
        for (int nj = 0; nj < 8; nj++) {
            int col = wn * 64 + nj * 8 + (lane & 3) * 2;
            *reinterpret_cast<float2*>(op + col) =
                make_float2(acc[mi][nj][0], acc[mi][nj][1]);
            *reinterpret_cast<float2*>(op + 8 * HW + col) =
                make_float2(acc[mi][nj][2], acc[mi][nj][3]);
        }
    }
}

// ---------------------------------------------------------------------------
// Plain inverse transform (initial Gr/Gu/Go convs)
// ---------------------------------------------------------------------------
__global__ void wg_inv_kernel(float* __restrict__ D0, float* __restrict__ D1,
                              float* __restrict__ D2) {
    int conv = blockIdx.y;
    const float* M = g_m + (size_t)conv * M_STRIDE;
    float* D = (conv == 0) ? D0 : (conv == 1) ? D1 : D2;
    int e = blockIdx.x * 256 + threadIdx.x;
    int co = e >> 8, t = e & (NT2 - 1);
    float y16[4][4];
    inv_read(M, co, t, y16);
    int ty = t >> 4, tx = t & 15;
    float* op = D + (size_t)co * HW + (4 * ty) * WW + 4 * tx;
#pragma unroll
    for (int i = 0; i < 4; i++)
        *reinterpret_cast<float4*>(op + i * WW) =
            make_float4(y16[i][0], y16[i][1], y16[i][2], y16[i][3]);
}

// ---------------------------------------------------------------------------
extern "C" void kernel_launch(void* const* d_in, const int* in_sizes, int n_in,
                              void* d_out, int out_size) {
    const float* vis  = (const float*)d_in[0];
    const float* lang = (const float*)d_in[1];
    const int*   adj  = (const int*)d_in[2];
    const float* mw   = (const float*)d_in[3];
    const float* mb   = (const float*)d_in[4];
    const float* rw   = (const float*)d_in[5];
    const float* rb   = (const float*)d_in[6];
    const float* uw   = (const float*)d_in[7];
    const float* ub   = (const float*)d_in[8];
    const float* ow   = (const float*)d_in[9];
    const float* ob   = (const float*)d_in[10];
    float* out = (float*)d_out;

    float* buf = nullptr;
    cudaGetSymbolAddress((void**)&buf, g_buf);
    __nv_bfloat16* wv = nullptr;
    cudaGetSymbolAddress((void**)&wv, g_wV);
    float* m = nullptr;
    cudaGetSymbolAddress((void**)&m, g_m);
    float* mr = nullptr;
    cudaGetSymbolAddress((void**)&mr, g_mr);
    __nv_bfloat16* V0 = wv;
    __nv_bfloat16* V1 = wv + VT_SLOT;
    __nv_bfloat16* V2 = wv + 2 * VT_SLOT;

    static bool init_done = false;
    if (!init_done) {
        cudaFuncSetAttribute(wg_gemm_kernel,
                             cudaFuncAttributeMaxDynamicSharedMemorySize, WG_SMEM);
        cudaFuncSetAttribute(wg_gemm_leaf_kernel,
                             cudaFuncAttributeMaxDynamicSharedMemorySize, WG_SMEM);
        cudaFuncSetAttribute(mc_gemm_kernel,
                             cudaFuncAttributeMaxDynamicSharedMemorySize, WG_SMEM);
        init_done = true;
    }

    dim3 wgrid1(2, 4, NJ);               // winograd gemm, 1 conv
    dim3 wgrid2(2, 4, 2 * NJ);           // 2 convs
    dim3 wgrid3(2, 4, 3 * NJ);           // 3 convs
    dim3 wgridL(2, 4, 6 * NJ);           // batched leaf R (6 node positions)
    dim3 mcg(32, 4);                     // mconv gemm
    dim3 inv3(512, 3);
    dim3 leafg(512, 6);

    prep_kernel<<<1, 32>>>(adj);
    langbias_kernel<<<40, 256>>>(lang, mw, mb);
    tapconst_kernel<<<54, 256>>>(rw, uw, ow);
    wg_wprep_kernel<<<6144, 256>>>(rw, uw, ow);
    mc_split_kernel<<<9216, 256>>>(vis, mw);

    // V-plane = conv1x1(vis, mconv_w[:, :512]) via split-bf16 mma
    mc_gemm_kernel<<<mcg, 128, WG_SMEM>>>(buf);
    wg_itrans_kernel<<<512, 256>>>(buf, V0);

    // shared convs of V (x-part weights of the 3 gates): Gr, Gu, Go
    wg_gemm_kernel<<<wgrid3, 128, WG_SMEM>>>(V0, 0, V0, 2, V0, 4,
                                             m, m + M_STRIDE, m + 2 * M_STRIDE, -1);
    wg_inv_kernel<<<inv3, 256>>>(buf + 1 * CHW, buf + 2 * CHW, buf + 3 * CHW);

    // ALL leaves upfront: h + forward transform + batched R GEMM,
    // 4 rounds of 6 node positions (g_m reused as 3 extra V slots here;
    // it is dead between wg_inv above and the first UO GEMM below).
    for (int r = 0; r < 4; r++) {
        leaf_combine_kernel<<<leafg, 256>>>(6 * r + 1, ub, ob);
        wg_gemm_leaf_kernel<<<wgridL, 128, WG_SMEM>>>(6 * r + 1);
    }

    // internal nodes in decreasing index (valid topological order);
    // node NND-1 is statically a leaf (handled above).
    for (int n = NND - 2; n >= 0; n--) {
        // fused gather (+R inverse) + forward transforms of cs, rh (skips leaf)
        gather_itrans_kernel<<<512, 256>>>(n, rb, V0, V1);
        // U = conv(cs, Wu_h), O = conv(rh, Wo_h) (skips leaf)
        wg_gemm_kernel<<<wgrid2, 128, WG_SMEM>>>(V0, 3, V1, 5, V1, 5,
                                                 m, m + M_STRIDE,
                                                 m + 2 * M_STRIDE, n);
        // fused inverse(U,O) + combine (+ h transform when n>0); skips leaf
        inv_combine_kernel<<<512, 256>>>(n, ub, ob, out, V2);
        if (n > 0)  // R[n] for internal n (leaf R done in batch above)
            wg_gemm_kernel<<<wgrid1, 128, WG_SMEM>>>(
                V2, 1, nullptr, 0, nullptr, 0,
                mr + (size_t)n * M_STRIDE, nullptr, nullptr, n);
    }
}